// round 5
// baseline (speedup 1.0000x reference)
#include <cuda_runtime.h>
#include <cuda_bf16.h>
#include <stdint.h>
#include <math.h>

#define D 256
#define MAXN 16384
#define MAXK 8192

// ---------------- scratch (module globals; no runtime allocation) ----------------
__device__ float          g_C[MAXK];          // per-code sum c^2
__device__ int            g_cand[MAXN * 4];   // top-4 candidates per row
__device__ int            g_idx[MAXN];        // final argmin per row
__device__ float          g_rowss[MAXN];      // per-row sum d^2
__device__ __nv_bfloat16  g_zb[MAXN * D];     // bf16 copy of z
__device__ __nv_bfloat16  g_cbb[MAXK * D];    // bf16 copy of codebook

// ================= tiny PTX helpers (all sm_80-legal) =================
__device__ __forceinline__ void cpa16(uint32_t dst, const void* src) {
    asm volatile("cp.async.cg.shared.global [%0], [%1], 16;" :: "r"(dst), "l"(src) : "memory");
}
#define CP_COMMIT() asm volatile("cp.async.commit_group;" ::: "memory")
#define CP_WAIT(n)  asm volatile("cp.async.wait_group %0;" :: "n"(n) : "memory")

__device__ __forceinline__ uint32_t smem_u32(const void* p) {
    uint32_t a;
    asm("{ .reg .u64 t; cvta.to.shared.u64 t, %1; cvt.u32.u64 %0, t; }" : "=r"(a) : "l"(p));
    return a;
}
__device__ __forceinline__ void ldsm_x4(uint32_t r[4], uint32_t addr) {
    asm volatile("ldmatrix.sync.aligned.m8n8.x4.shared.b16 {%0,%1,%2,%3}, [%4];"
        : "=r"(r[0]), "=r"(r[1]), "=r"(r[2]), "=r"(r[3]) : "r"(addr));
}
// D += A(16x16 bf16, row-major) * B(16x8 col-major)
__device__ __forceinline__ void mma_bf16(float c[4], const uint32_t a[4], uint32_t b0, uint32_t b1) {
    asm volatile(
        "mma.sync.aligned.m16n8k16.row.col.f32.bf16.bf16.f32 "
        "{%0,%1,%2,%3}, {%4,%5,%6,%7}, {%8,%9}, {%0,%1,%2,%3};"
        : "+f"(c[0]), "+f"(c[1]), "+f"(c[2]), "+f"(c[3])
        : "r"(a[0]), "r"(a[1]), "r"(a[2]), "r"(a[3]), "r"(b0), "r"(b1));
}

// ================= f32 -> bf16 conversion (z) =================
__global__ void k_cvt(const float* __restrict__ src, __nv_bfloat16* __restrict__ dst, int n4) {
    int i = blockIdx.x * blockDim.x + threadIdx.x;
    if (i >= n4) return;
    float4 v = reinterpret_cast<const float4*>(src)[i];
    __nv_bfloat162 h0 = __floats2bfloat162_rn(v.x, v.y);
    __nv_bfloat162 h1 = __floats2bfloat162_rn(v.z, v.w);
    reinterpret_cast<__nv_bfloat162*>(dst)[i * 2]     = h0;
    reinterpret_cast<__nv_bfloat162*>(dst)[i * 2 + 1] = h1;
}

// ===== codebook prep: bf16 conversion + exact sequential sum(c^2) fused =====
__global__ void k_prep_cb(const float* __restrict__ cb, __nv_bfloat16* __restrict__ dst, int K) {
    int r = blockIdx.x * blockDim.x + threadIdx.x;
    if (r >= K) return;
    const float4* p = reinterpret_cast<const float4*>(cb + (size_t)r * D);
    __nv_bfloat162* o = reinterpret_cast<__nv_bfloat162*>(dst + (size_t)r * D);
    float a = 0.f;
#pragma unroll 8
    for (int i = 0; i < D / 4; ++i) {
        float4 v = p[i];
        a = __fadd_rn(a, __fmul_rn(v.x, v.x));
        a = __fadd_rn(a, __fmul_rn(v.y, v.y));
        a = __fadd_rn(a, __fmul_rn(v.z, v.z));
        a = __fadd_rn(a, __fmul_rn(v.w, v.w));
        o[i * 2]     = __floats2bfloat162_rn(v.x, v.y);
        o[i * 2 + 1] = __floats2bfloat162_rn(v.z, v.w);
    }
    g_C[r] = a;
}

// ================= stage 1: HMMA bf16 GEMM + per-row top-4 =================
// CTA: 128 rows x all K codes, chunks of 128 codes. 512 threads = 16 warps (4M x 4N).
// Warp tile 32 rows x 32 codes. smem rows padded to 528B -> conflict-free LDSM.
#define PADW 132
#define PADB 528
#define SM_A  0
#define SM_B0 67584
#define SM_B1 135168
#define SM_TOT 202752

__global__ __launch_bounds__(512, 1)
void k_gemm_topk(int K) {
    extern __shared__ char sm[];
    const uint32_t sb = smem_u32(sm);
    const int tid = threadIdx.x;
    const int lid = tid & 31, wid = tid >> 5;
    const int warpM = wid & 3, warpN = wid >> 2;
    const int g = lid >> 2, tg = lid & 3;
    const int row0 = blockIdx.x * 128;
    const int nchunks = K / 128;   // 64

    // ---- load A (128 rows x 256 bf16) via cp.async ----
    {
        const __nv_bfloat16* zsrc = g_zb + (size_t)row0 * D;
#pragma unroll
        for (int t = 0; t < 8; ++t) {
            int e = t * 512 + tid;          // 0..4095
            int r = e >> 5, j = e & 31;
            cpa16(sb + SM_A + r * PADB + j * 16, zsrc + (size_t)r * D + j * 8);
        }
    }
    // ---- prefetch B chunk 0 ----
    {
#pragma unroll
        for (int t = 0; t < 8; ++t) {
            int e = t * 512 + tid;
            int r = e >> 5, j = e & 31;
            cpa16(sb + SM_B0 + r * PADB + j * 16, g_cbb + (size_t)r * D + j * 8);
        }
    }
    CP_COMMIT();

    // ldmatrix lane address components
    const int aLane = (lid & 15);
    const int aKoff = (lid >> 4) * 16;
    // B x4: lanes 0-7 -> codes +0..7 k-lo, 8-15 -> same codes k-hi,
    //       16-23 -> codes +8..15 k-lo, 24-31 -> k-hi
    const int bCode = (lid & 7) + ((lid >> 4) << 3);
    const int bKoff = ((lid >> 3) & 1) * 16;

    uint32_t aAddr[2];
#pragma unroll
    for (int mt = 0; mt < 2; ++mt)
        aAddr[mt] = sb + SM_A + (uint32_t)(warpM * 32 + mt * 16 + aLane) * PADB + aKoff;

    // per-thread top-4 for each of its 4 tracked rows
    float bv[4][4];
    int   bi[4][4];
#pragma unroll
    for (int i = 0; i < 4; ++i)
#pragma unroll
        for (int j = 0; j < 4; ++j) { bv[i][j] = -3.4e38f; bi[i][j] = 0; }

    for (int i = 0; i < nchunks; ++i) {
        const int s = i & 1;
        if (i + 1 < nchunks) {
            const int sn = (i + 1) & 1;
            const __nv_bfloat16* csrc = g_cbb + (size_t)(i + 1) * 128 * D;
            const uint32_t dstb = sb + (sn ? SM_B1 : SM_B0);
#pragma unroll
            for (int t = 0; t < 8; ++t) {
                int e = t * 512 + tid;
                int r = e >> 5, j = e & 31;
                cpa16(dstb + r * PADB + j * 16, csrc + (size_t)r * D + j * 8);
            }
            CP_COMMIT();
            CP_WAIT(1);
        } else {
            CP_WAIT(0);
        }
        __syncthreads();

        // two x4 B bases: p=0 covers codes [0,16), p=1 covers [16,32) of warp tile
        uint32_t bAddr[2];
#pragma unroll
        for (int p = 0; p < 2; ++p)
            bAddr[p] = sb + (s ? SM_B1 : SM_B0)
                     + (uint32_t)(warpN * 32 + p * 16 + bCode) * PADB + bKoff;

        float acc[2][4][4];
#pragma unroll
        for (int mt = 0; mt < 2; ++mt)
#pragma unroll
            for (int nt = 0; nt < 4; ++nt)
#pragma unroll
                for (int q = 0; q < 4; ++q) acc[mt][nt][q] = 0.f;

#pragma unroll
        for (int ks = 0; ks < 16; ++ks) {
            uint32_t a[2][4];
            ldsm_x4(a[0], aAddr[0] + ks * 32);
            ldsm_x4(a[1], aAddr[1] + ks * 32);
#pragma unroll
            for (int p = 0; p < 2; ++p) {
                uint32_t b[4];
                ldsm_x4(b, bAddr[p] + ks * 32);
                mma_bf16(acc[0][2 * p],     a[0], b[0], b[1]);
                mma_bf16(acc[1][2 * p],     a[1], b[0], b[1]);
                mma_bf16(acc[0][2 * p + 1], a[0], b[2], b[3]);
                mma_bf16(acc[1][2 * p + 1], a[1], b[2], b[3]);
            }
        }

        // ---- top-4 update (index computed lazily, only on insert) ----
        const int cbase0 = i * 128 + warpN * 32 + tg * 2;
#pragma unroll
        for (int mt = 0; mt < 2; ++mt) {
#pragma unroll
            for (int nt = 0; nt < 4; ++nt) {
#pragma unroll
                for (int q = 0; q < 4; ++q) {
                    const int tr = mt * 2 + (q >> 1);
                    const float v = acc[mt][nt][q];
                    if (v > bv[tr][3]) {
                        const int ci = cbase0 + nt * 8 + (q & 1);
                        if (v > bv[tr][0]) {
                            bv[tr][3]=bv[tr][2]; bi[tr][3]=bi[tr][2];
                            bv[tr][2]=bv[tr][1]; bi[tr][2]=bi[tr][1];
                            bv[tr][1]=bv[tr][0]; bi[tr][1]=bi[tr][0];
                            bv[tr][0]=v; bi[tr][0]=ci;
                        } else if (v > bv[tr][1]) {
                            bv[tr][3]=bv[tr][2]; bi[tr][3]=bi[tr][2];
                            bv[tr][2]=bv[tr][1]; bi[tr][2]=bi[tr][1];
                            bv[tr][1]=v; bi[tr][1]=ci;
                        } else if (v > bv[tr][2]) {
                            bv[tr][3]=bv[tr][2]; bi[tr][3]=bi[tr][2];
                            bv[tr][2]=v; bi[tr][2]=ci;
                        } else {
                            bv[tr][3]=v; bi[tr][3]=ci;
                        }
                    }
                }
            }
        }
        __syncthreads();
    }

    // ---- merge: 16 owners x top4 per row -> global top4 ----
    // transposed layout: mv[entry*128 + srow] -> conflict-free reads
    float* mv = reinterpret_cast<float*>(sm);           // 64*128 floats = 32KB
    int*   mi = reinterpret_cast<int*>(sm + 32768);     // 32KB
    const int owner = warpN * 4 + tg;                   // 0..15
#pragma unroll
    for (int tr = 0; tr < 4; ++tr) {
        const int srow = warpM * 32 + (tr >> 1) * 16 + (tr & 1) * 8 + g;
#pragma unroll
        for (int j = 0; j < 4; ++j) {
            mv[(owner * 4 + j) * 128 + srow] = bv[tr][j];
            mi[(owner * 4 + j) * 128 + srow] = bi[tr][j];
        }
    }
    __syncthreads();
    if (tid < 128) {
        float fv0=-3.4e38f, fv1=-3.4e38f, fv2=-3.4e38f, fv3=-3.4e38f;
        int   fi0=0, fi1=0, fi2=0, fi3=0;
#pragma unroll 4
        for (int e = 0; e < 64; ++e) {
            float v = mv[e * 128 + tid];
            if (v > fv3) {
                int ci = mi[e * 128 + tid];
                if (v > fv0)      { fv3=fv2;fi3=fi2; fv2=fv1;fi2=fi1; fv1=fv0;fi1=fi0; fv0=v;fi0=ci; }
                else if (v > fv1) { fv3=fv2;fi3=fi2; fv2=fv1;fi2=fi1; fv1=v;fi1=ci; }
                else if (v > fv2) { fv3=fv2;fi3=fi2; fv2=v;fi2=ci; }
                else              { fv3=v;fi3=ci; }
            }
        }
        const int r = row0 + tid;
        g_cand[r * 4 + 0] = fi0;
        g_cand[r * 4 + 1] = fi1;
        g_cand[r * 4 + 2] = fi2;
        g_cand[r * 4 + 3] = fi3;
    }
}

// ================= stage 2: exact fp32 rescore of 4 candidates =================
// Bit-identical arithmetic to the R1 full scan: sequential-k fmaf dot,
// fl(A-2B)+C, min by (value, index).
__global__ void k_rescore(const float* __restrict__ z, const float* __restrict__ cb, int n) {
    int row = blockIdx.x * blockDim.x + threadIdx.x;
    if (row >= n) return;
    const float4* zr = reinterpret_cast<const float4*>(z + (size_t)row * D);

    float A = 0.f;
#pragma unroll 8
    for (int i = 0; i < D / 4; ++i) {
        float4 v = zr[i];
        A = __fadd_rn(A, __fmul_rn(v.x, v.x));
        A = __fadd_rn(A, __fmul_rn(v.y, v.y));
        A = __fadd_rn(A, __fmul_rn(v.z, v.z));
        A = __fadd_rn(A, __fmul_rn(v.w, v.w));
    }

    float bestv = 3.4e38f;
    int   besti = 0x7fffffff;
#pragma unroll
    for (int m = 0; m < 4; ++m) {
        const int c = g_cand[row * 4 + m];
        const float4* cr = reinterpret_cast<const float4*>(cb + (size_t)c * D);
        float acc = 0.f;
#pragma unroll 8
        for (int i = 0; i < D / 4; ++i) {
            float4 a = zr[i];
            float4 b = cr[i];
            acc = __fmaf_rn(a.x, b.x, acc);
            acc = __fmaf_rn(a.y, b.y, acc);
            acc = __fmaf_rn(a.z, b.z, acc);
            acc = __fmaf_rn(a.w, b.w, acc);
        }
        float s = __fadd_rn(__fmaf_rn(-2.f, acc, A), g_C[c]);
        if (s < bestv || (s == bestv && c < besti)) { bestv = s; besti = c; }
    }
    g_idx[row] = besti;
}

// ================= finish: gather, z_q, per-row d^2, indices =================
__global__ void k_finish(const float* __restrict__ z, const float* __restrict__ cb,
                         float* __restrict__ zq, float* __restrict__ idxout) {
    const int row = blockIdx.x;
    const int t = threadIdx.x;          // 128 threads, 2 elems each
    const int code = g_idx[row];
    const float2 zp = reinterpret_cast<const float2*>(z + (size_t)row * D)[t];
    const float2 cp = reinterpret_cast<const float2*>(cb + (size_t)code * D)[t];
    float d0 = __fsub_rn(cp.x, zp.x);
    float d1 = __fsub_rn(cp.y, zp.y);
    float ss = __fadd_rn(__fmul_rn(d0, d0), __fmul_rn(d1, d1));

    __shared__ float red[4];
#pragma unroll
    for (int o = 16; o > 0; o >>= 1)
        ss = __fadd_rn(ss, __shfl_xor_sync(0xffffffffu, ss, o));
    if ((t & 31) == 0) red[t >> 5] = ss;
    __syncthreads();
    float ssum = __fadd_rn(__fadd_rn(red[0], red[1]), __fadd_rn(red[2], red[3]));

    float mag = __fsqrt_rn(ssum);
    float den = __fadd_rn(mag, 1e-8f);
    float q0 = __fadd_rn(zp.x, __fmul_rn(mag, __fdiv_rn(d0, den)));
    float q1 = __fadd_rn(zp.y, __fmul_rn(mag, __fdiv_rn(d1, den)));
    float2 o; o.x = q0; o.y = q1;
    reinterpret_cast<float2*>(zq + (size_t)row * D)[t] = o;
    if (t == 0) {
        g_rowss[row] = ssum;
        idxout[row] = (float)code;
    }
}

// ================= loss = 1.25 * mean(d^2) =================
__global__ void k_loss(float* __restrict__ out_loss, int n) {
    __shared__ double sred[256];
    double s = 0.0;
    for (int i = threadIdx.x; i < n; i += 256) s += (double)g_rowss[i];
    sred[threadIdx.x] = s;
    __syncthreads();
    for (int o = 128; o > 0; o >>= 1) {
        if (threadIdx.x < o) sred[threadIdx.x] += sred[threadIdx.x + o];
        __syncthreads();
    }
    if (threadIdx.x == 0) {
        double mean = sred[0] / ((double)n * (double)D);
        out_loss[0] = (float)(1.25 * mean);
    }
}

extern "C" void kernel_launch(void* const* d_in, const int* in_sizes, int n_in,
                              void* d_out, int out_size) {
    const float* z  = (const float*)d_in[0];
    const float* cb = (const float*)d_in[1];
    const int n = in_sizes[0] / D;   // 16384
    const int K = in_sizes[1] / D;   // 8192

    float* out    = (float*)d_out;
    float* zq     = out;
    float* loss   = out + (size_t)n * D;
    float* idxout = loss + 1;

    cudaFuncSetAttribute(k_gemm_topk, cudaFuncAttributeMaxDynamicSharedMemorySize, SM_TOT);

    __nv_bfloat16* zb;  cudaGetSymbolAddress((void**)&zb,  g_zb);
    __nv_bfloat16* cbb; cudaGetSymbolAddress((void**)&cbb, g_cbb);

    k_cvt<<<(n * D / 4 + 255) / 256, 256>>>(z, zb, n * D / 4);
    k_prep_cb<<<(K + 255) / 256, 256>>>(cb, cbb, K);
    k_gemm_topk<<<n / 128, 512, SM_TOT>>>(K);
    k_rescore<<<(n + 255) / 256, 256>>>(z, cb, n);
    k_finish<<<n, 128>>>(z, cb, zq, idxout);
    k_loss<<<1, 256>>>(loss, n);
}

// round 6
// speedup vs baseline: 1.3847x; 1.3847x over previous
#include <cuda_runtime.h>
#include <cuda_bf16.h>
#include <stdint.h>
#include <math.h>

#define D 256
#define MAXN 16384
#define MAXK 8192

// ---------------- scratch (module globals; no runtime allocation) ----------------
__device__ float          g_A[MAXN];          // per-row sum z^2 (exact sequential)
__device__ float          g_C[MAXK];          // per-code sum c^2
__device__ int            g_cand[MAXN * 4];   // top-4 candidates per row
__device__ int            g_idx[MAXN];        // final argmin per row
__device__ float          g_rowss[MAXN];      // per-row sum d^2
__device__ __nv_bfloat16  g_zb[MAXN * D];     // bf16 copy of z
__device__ __nv_bfloat16  g_cbb[MAXK * D];    // bf16 copy of codebook

// ================= tiny PTX helpers (all sm_80-legal) =================
__device__ __forceinline__ void cpa16(uint32_t dst, const void* src) {
    asm volatile("cp.async.cg.shared.global [%0], [%1], 16;" :: "r"(dst), "l"(src) : "memory");
}
#define CP_COMMIT() asm volatile("cp.async.commit_group;" ::: "memory")
#define CP_WAIT(n)  asm volatile("cp.async.wait_group %0;" :: "n"(n) : "memory")

__device__ __forceinline__ uint32_t smem_u32(const void* p) {
    uint32_t a;
    asm("{ .reg .u64 t; cvta.to.shared.u64 t, %1; cvt.u32.u64 %0, t; }" : "=r"(a) : "l"(p));
    return a;
}
__device__ __forceinline__ void ldsm_x4(uint32_t r[4], uint32_t addr) {
    asm volatile("ldmatrix.sync.aligned.m8n8.x4.shared.b16 {%0,%1,%2,%3}, [%4];"
        : "=r"(r[0]), "=r"(r[1]), "=r"(r[2]), "=r"(r[3]) : "r"(addr));
}
// D += A(16x16 bf16, row-major) * B(16x8 col-major)
__device__ __forceinline__ void mma_bf16(float c[4], const uint32_t a[4], uint32_t b0, uint32_t b1) {
    asm volatile(
        "mma.sync.aligned.m16n8k16.row.col.f32.bf16.bf16.f32 "
        "{%0,%1,%2,%3}, {%4,%5,%6,%7}, {%8,%9}, {%0,%1,%2,%3};"
        : "+f"(c[0]), "+f"(c[1]), "+f"(c[2]), "+f"(c[3])
        : "r"(a[0]), "r"(a[1]), "r"(a[2]), "r"(a[3]), "r"(b0), "r"(b1));
}

// ===== z prep: bf16 conversion + exact sequential sum(z^2) fused =====
__global__ void k_prep_z(const float* __restrict__ z, __nv_bfloat16* __restrict__ dst, int n) {
    int r = blockIdx.x * blockDim.x + threadIdx.x;
    if (r >= n) return;
    const float4* p = reinterpret_cast<const float4*>(z + (size_t)r * D);
    __nv_bfloat162* o = reinterpret_cast<__nv_bfloat162*>(dst + (size_t)r * D);
    float a = 0.f;
#pragma unroll 8
    for (int i = 0; i < D / 4; ++i) {
        float4 v = p[i];
        a = __fadd_rn(a, __fmul_rn(v.x, v.x));
        a = __fadd_rn(a, __fmul_rn(v.y, v.y));
        a = __fadd_rn(a, __fmul_rn(v.z, v.z));
        a = __fadd_rn(a, __fmul_rn(v.w, v.w));
        o[i * 2]     = __floats2bfloat162_rn(v.x, v.y);
        o[i * 2 + 1] = __floats2bfloat162_rn(v.z, v.w);
    }
    g_A[r] = a;
}

// ===== codebook prep: bf16 conversion + exact sequential sum(c^2) fused =====
__global__ void k_prep_cb(const float* __restrict__ cb, __nv_bfloat16* __restrict__ dst, int K) {
    int r = blockIdx.x * blockDim.x + threadIdx.x;
    if (r >= K) return;
    const float4* p = reinterpret_cast<const float4*>(cb + (size_t)r * D);
    __nv_bfloat162* o = reinterpret_cast<__nv_bfloat162*>(dst + (size_t)r * D);
    float a = 0.f;
#pragma unroll 8
    for (int i = 0; i < D / 4; ++i) {
        float4 v = p[i];
        a = __fadd_rn(a, __fmul_rn(v.x, v.x));
        a = __fadd_rn(a, __fmul_rn(v.y, v.y));
        a = __fadd_rn(a, __fmul_rn(v.z, v.z));
        a = __fadd_rn(a, __fmul_rn(v.w, v.w));
        o[i * 2]     = __floats2bfloat162_rn(v.x, v.y);
        o[i * 2 + 1] = __floats2bfloat162_rn(v.z, v.w);
    }
    g_C[r] = a;
}

// ================= stage 1: HMMA bf16 GEMM + per-row candidates =================
// CTA: 128 rows x all K codes, chunks of 128 codes. 512 threads = 16 warps (4M x 4N).
// Warp tile 32 rows x 32 codes. smem rows padded to 528B -> conflict-free LDSM.
// Per (thread, row-slot) top-2; merge 32 entries/row -> global top-4.
#define PADW 132
#define PADB 528
#define SM_A  0
#define SM_B0 67584
#define SM_B1 135168
#define SM_TOT 202752

__global__ __launch_bounds__(512, 1)
void k_gemm_topk(int K) {
    extern __shared__ char sm[];
    const uint32_t sb = smem_u32(sm);
    const int tid = threadIdx.x;
    const int lid = tid & 31, wid = tid >> 5;
    const int warpM = wid & 3, warpN = wid >> 2;
    const int g = lid >> 2, tg = lid & 3;
    const int row0 = blockIdx.x * 128;
    const int nchunks = K / 128;   // 64

    // ---- load A (128 rows x 256 bf16) via cp.async ----
    {
        const __nv_bfloat16* zsrc = g_zb + (size_t)row0 * D;
#pragma unroll
        for (int t = 0; t < 8; ++t) {
            int e = t * 512 + tid;          // 0..4095
            int r = e >> 5, j = e & 31;
            cpa16(sb + SM_A + r * PADB + j * 16, zsrc + (size_t)r * D + j * 8);
        }
    }
    // ---- prefetch B chunk 0 ----
    {
#pragma unroll
        for (int t = 0; t < 8; ++t) {
            int e = t * 512 + tid;
            int r = e >> 5, j = e & 31;
            cpa16(sb + SM_B0 + r * PADB + j * 16, g_cbb + (size_t)r * D + j * 8);
        }
    }
    CP_COMMIT();

    // ldmatrix lane address components
    const int aLane = (lid & 15);
    const int aKoff = (lid >> 4) * 16;
    const int bCode = (lid & 7) + ((lid >> 4) << 3);
    const int bKoff = ((lid >> 3) & 1) * 16;

    uint32_t aAddr[2];
#pragma unroll
    for (int mt = 0; mt < 2; ++mt)
        aAddr[mt] = sb + SM_A + (uint32_t)(warpM * 32 + mt * 16 + aLane) * PADB + aKoff;

    // per-thread top-2 for each of its 4 tracked rows
    float bv[4][2];
    int   bi[4][2];
#pragma unroll
    for (int i = 0; i < 4; ++i) { bv[i][0] = bv[i][1] = -3.4e38f; bi[i][0] = bi[i][1] = 0; }

    for (int i = 0; i < nchunks; ++i) {
        const int s = i & 1;
        if (i + 1 < nchunks) {
            const int sn = (i + 1) & 1;
            const __nv_bfloat16* csrc = g_cbb + (size_t)(i + 1) * 128 * D;
            const uint32_t dstb = sb + (sn ? SM_B1 : SM_B0);
#pragma unroll
            for (int t = 0; t < 8; ++t) {
                int e = t * 512 + tid;
                int r = e >> 5, j = e & 31;
                cpa16(dstb + r * PADB + j * 16, csrc + (size_t)r * D + j * 8);
            }
            CP_COMMIT();
            CP_WAIT(1);
        } else {
            CP_WAIT(0);
        }
        __syncthreads();

        uint32_t bAddr[2];
#pragma unroll
        for (int p = 0; p < 2; ++p)
            bAddr[p] = sb + (s ? SM_B1 : SM_B0)
                     + (uint32_t)(warpN * 32 + p * 16 + bCode) * PADB + bKoff;

        float acc[2][4][4];
#pragma unroll
        for (int mt = 0; mt < 2; ++mt)
#pragma unroll
            for (int nt = 0; nt < 4; ++nt)
#pragma unroll
                for (int q = 0; q < 4; ++q) acc[mt][nt][q] = 0.f;

        // ---- software-pipelined fragment feed: 2 k-steps in flight ----
        uint32_t a0[2][4], b0[2][4], a1[2][4], b1[2][4];
        ldsm_x4(a0[0], aAddr[0]);
        ldsm_x4(a0[1], aAddr[1]);
        ldsm_x4(b0[0], bAddr[0]);
        ldsm_x4(b0[1], bAddr[1]);
#pragma unroll
        for (int kk = 0; kk < 16; kk += 2) {
            // prefetch kk+1 fragments
            ldsm_x4(a1[0], aAddr[0] + (kk + 1) * 32);
            ldsm_x4(a1[1], aAddr[1] + (kk + 1) * 32);
            ldsm_x4(b1[0], bAddr[0] + (kk + 1) * 32);
            ldsm_x4(b1[1], bAddr[1] + (kk + 1) * 32);
            // compute kk
#pragma unroll
            for (int p = 0; p < 2; ++p) {
                mma_bf16(acc[0][2 * p],     a0[0], b0[p][0], b0[p][1]);
                mma_bf16(acc[1][2 * p],     a0[1], b0[p][0], b0[p][1]);
                mma_bf16(acc[0][2 * p + 1], a0[0], b0[p][2], b0[p][3]);
                mma_bf16(acc[1][2 * p + 1], a0[1], b0[p][2], b0[p][3]);
            }
            // prefetch kk+2 fragments
            if (kk + 2 < 16) {
                ldsm_x4(a0[0], aAddr[0] + (kk + 2) * 32);
                ldsm_x4(a0[1], aAddr[1] + (kk + 2) * 32);
                ldsm_x4(b0[0], bAddr[0] + (kk + 2) * 32);
                ldsm_x4(b0[1], bAddr[1] + (kk + 2) * 32);
            }
            // compute kk+1
#pragma unroll
            for (int p = 0; p < 2; ++p) {
                mma_bf16(acc[0][2 * p],     a1[0], b1[p][0], b1[p][1]);
                mma_bf16(acc[1][2 * p],     a1[1], b1[p][0], b1[p][1]);
                mma_bf16(acc[0][2 * p + 1], a1[0], b1[p][2], b1[p][3]);
                mma_bf16(acc[1][2 * p + 1], a1[1], b1[p][2], b1[p][3]);
            }
        }

        // ---- top-2 update (index computed lazily, only on insert) ----
        const int cbase0 = i * 128 + warpN * 32 + tg * 2;
#pragma unroll
        for (int mt = 0; mt < 2; ++mt) {
#pragma unroll
            for (int nt = 0; nt < 4; ++nt) {
#pragma unroll
                for (int q = 0; q < 4; ++q) {
                    const int tr = mt * 2 + (q >> 1);
                    const float v = acc[mt][nt][q];
                    if (v > bv[tr][1]) {
                        const int ci = cbase0 + nt * 8 + (q & 1);
                        if (v > bv[tr][0]) {
                            bv[tr][1] = bv[tr][0]; bi[tr][1] = bi[tr][0];
                            bv[tr][0] = v;         bi[tr][0] = ci;
                        } else {
                            bv[tr][1] = v;         bi[tr][1] = ci;
                        }
                    }
                }
            }
        }
        __syncthreads();
    }

    // ---- merge: 16 owners x top2 per row -> global top4 ----
    // transposed layout: mv[entry*128 + srow] -> conflict-free reads
    float* mv = reinterpret_cast<float*>(sm);           // 32*128 floats = 16KB
    int*   mi = reinterpret_cast<int*>(sm + 16384);     // 16KB
    const int owner = warpN * 4 + tg;                   // 0..15
#pragma unroll
    for (int tr = 0; tr < 4; ++tr) {
        const int srow = warpM * 32 + (tr >> 1) * 16 + (tr & 1) * 8 + g;
#pragma unroll
        for (int j = 0; j < 2; ++j) {
            mv[(owner * 2 + j) * 128 + srow] = bv[tr][j];
            mi[(owner * 2 + j) * 128 + srow] = bi[tr][j];
        }
    }
    __syncthreads();
    if (tid < 128) {
        float fv0=-3.4e38f, fv1=-3.4e38f, fv2=-3.4e38f, fv3=-3.4e38f;
        int   fi0=0, fi1=0, fi2=0, fi3=0;
#pragma unroll 4
        for (int e = 0; e < 32; ++e) {
            float v = mv[e * 128 + tid];
            if (v > fv3) {
                int ci = mi[e * 128 + tid];
                if (v > fv0)      { fv3=fv2;fi3=fi2; fv2=fv1;fi2=fi1; fv1=fv0;fi1=fi0; fv0=v;fi0=ci; }
                else if (v > fv1) { fv3=fv2;fi3=fi2; fv2=fv1;fi2=fi1; fv1=v;fi1=ci; }
                else if (v > fv2) { fv3=fv2;fi3=fi2; fv2=v;fi2=ci; }
                else              { fv3=v;fi3=ci; }
            }
        }
        const int r = row0 + tid;
        g_cand[r * 4 + 0] = fi0;
        g_cand[r * 4 + 1] = fi1;
        g_cand[r * 4 + 2] = fi2;
        g_cand[r * 4 + 3] = fi3;
    }
}

// ================= stage 2: exact fp32 rescore, 4 lanes per row =================
// Each lane computes one candidate's sequential-k fmaf dot (identical order to
// the R1 full scan), score = fl(fl(A-2B)+C); min-by-(value,index) shfl butterfly
// is identical to the sequential m-loop min.
__global__ void k_rescore(const float* __restrict__ z, const float* __restrict__ cb, int n) {
    int gid = blockIdx.x * blockDim.x + threadIdx.x;
    int row = gid >> 2, m = gid & 3;
    if (row >= n) return;
    const float4* zr = reinterpret_cast<const float4*>(z + (size_t)row * D);

    const float A = g_A[row];
    int c = g_cand[row * 4 + m];
    const float4* cr = reinterpret_cast<const float4*>(cb + (size_t)c * D);

    float acc = 0.f;
#pragma unroll 8
    for (int i = 0; i < D / 4; ++i) {
        float4 a = zr[i];
        float4 b = cr[i];
        acc = __fmaf_rn(a.x, b.x, acc);
        acc = __fmaf_rn(a.y, b.y, acc);
        acc = __fmaf_rn(a.z, b.z, acc);
        acc = __fmaf_rn(a.w, b.w, acc);
    }
    float s = __fadd_rn(__fmaf_rn(-2.f, acc, A), g_C[c]);

#pragma unroll
    for (int o = 1; o < 4; o <<= 1) {
        float sv = __shfl_xor_sync(0xffffffffu, s, o);
        int   ci = __shfl_xor_sync(0xffffffffu, c, o);
        if (sv < s || (sv == s && ci < c)) { s = sv; c = ci; }
    }
    if (m == 0) g_idx[row] = c;
}

// ================= finish: gather, z_q, per-row d^2, indices =================
__global__ void k_finish(const float* __restrict__ z, const float* __restrict__ cb,
                         float* __restrict__ zq, float* __restrict__ idxout) {
    const int row = blockIdx.x;
    const int t = threadIdx.x;          // 128 threads, 2 elems each
    const int code = g_idx[row];
    const float2 zp = reinterpret_cast<const float2*>(z + (size_t)row * D)[t];
    const float2 cp = reinterpret_cast<const float2*>(cb + (size_t)code * D)[t];
    float d0 = __fsub_rn(cp.x, zp.x);
    float d1 = __fsub_rn(cp.y, zp.y);
    float ss = __fadd_rn(__fmul_rn(d0, d0), __fmul_rn(d1, d1));

    __shared__ float red[4];
#pragma unroll
    for (int o = 16; o > 0; o >>= 1)
        ss = __fadd_rn(ss, __shfl_xor_sync(0xffffffffu, ss, o));
    if ((t & 31) == 0) red[t >> 5] = ss;
    __syncthreads();
    float ssum = __fadd_rn(__fadd_rn(red[0], red[1]), __fadd_rn(red[2], red[3]));

    float mag = __fsqrt_rn(ssum);
    float den = __fadd_rn(mag, 1e-8f);
    float q0 = __fadd_rn(zp.x, __fmul_rn(mag, __fdiv_rn(d0, den)));
    float q1 = __fadd_rn(zp.y, __fmul_rn(mag, __fdiv_rn(d1, den)));
    float2 o; o.x = q0; o.y = q1;
    reinterpret_cast<float2*>(zq + (size_t)row * D)[t] = o;
    if (t == 0) {
        g_rowss[row] = ssum;
        idxout[row] = (float)code;
    }
}

// ================= loss = 1.25 * mean(d^2) =================
__global__ void k_loss(float* __restrict__ out_loss, int n) {
    __shared__ double sred[256];
    double s = 0.0;
    for (int i = threadIdx.x; i < n; i += 256) s += (double)g_rowss[i];
    sred[threadIdx.x] = s;
    __syncthreads();
    for (int o = 128; o > 0; o >>= 1) {
        if (threadIdx.x < o) sred[threadIdx.x] += sred[threadIdx.x + o];
        __syncthreads();
    }
    if (threadIdx.x == 0) {
        double mean = sred[0] / ((double)n * (double)D);
        out_loss[0] = (float)(1.25 * mean);
    }
}

extern "C" void kernel_launch(void* const* d_in, const int* in_sizes, int n_in,
                              void* d_out, int out_size) {
    const float* z  = (const float*)d_in[0];
    const float* cb = (const float*)d_in[1];
    const int n = in_sizes[0] / D;   // 16384
    const int K = in_sizes[1] / D;   // 8192

    float* out    = (float*)d_out;
    float* zq     = out;
    float* loss   = out + (size_t)n * D;
    float* idxout = loss + 1;

    cudaFuncSetAttribute(k_gemm_topk, cudaFuncAttributeMaxDynamicSharedMemorySize, SM_TOT);

    __nv_bfloat16* zb;  cudaGetSymbolAddress((void**)&zb,  g_zb);
    __nv_bfloat16* cbb; cudaGetSymbolAddress((void**)&cbb, g_cbb);

    k_prep_z<<<(n + 255) / 256, 256>>>(z, zb, n);
    k_prep_cb<<<(K + 255) / 256, 256>>>(cb, cbb, K);
    k_gemm_topk<<<n / 128, 512, SM_TOT>>>(K);
    k_rescore<<<(n * 4 + 255) / 256, 256>>>(z, cb, n);
    k_finish<<<n, 128>>>(z, cb, zq, idxout);
    k_loss<<<1, 256>>>(loss, n);
}

// round 7
// speedup vs baseline: 1.4760x; 1.0659x over previous
#include <cuda_runtime.h>
#include <cuda_bf16.h>
#include <stdint.h>
#include <math.h>

#define D 256
#define MAXN 16384
#define MAXK 8192

// ---------------- scratch (module globals; no runtime allocation) ----------------
__device__ float          g_A[MAXN];          // per-row sum z^2 (exact sequential)
__device__ float          g_C[MAXK];          // per-code sum c^2
__device__ int            g_cand[MAXN * 4];   // top-4 candidates per row
__device__ int            g_idx[MAXN];        // final argmin per row
__device__ float          g_rowss[MAXN];      // per-row sum d^2
__device__ __nv_bfloat16  g_zb[MAXN * D];     // bf16 copy of z
__device__ __nv_bfloat16  g_cbb[MAXK * D];    // bf16 copy of codebook

// ================= tiny PTX helpers (all sm_80-legal) =================
__device__ __forceinline__ void cpa16(uint32_t dst, const void* src) {
    asm volatile("cp.async.cg.shared.global [%0], [%1], 16;" :: "r"(dst), "l"(src) : "memory");
}
#define CP_COMMIT() asm volatile("cp.async.commit_group;" ::: "memory")
#define CP_WAIT(n)  asm volatile("cp.async.wait_group %0;" :: "n"(n) : "memory")

__device__ __forceinline__ uint32_t smem_u32(const void* p) {
    uint32_t a;
    asm("{ .reg .u64 t; cvta.to.shared.u64 t, %1; cvt.u32.u64 %0, t; }" : "=r"(a) : "l"(p));
    return a;
}
__device__ __forceinline__ void ldsm_x4(uint32_t r[4], uint32_t addr) {
    asm volatile("ldmatrix.sync.aligned.m8n8.x4.shared.b16 {%0,%1,%2,%3}, [%4];"
        : "=r"(r[0]), "=r"(r[1]), "=r"(r[2]), "=r"(r[3]) : "r"(addr));
}
// D += A(16x16 bf16, row-major) * B(16x8 col-major)
__device__ __forceinline__ void mma_bf16(float c[4], const uint32_t a[4], uint32_t b0, uint32_t b1) {
    asm volatile(
        "mma.sync.aligned.m16n8k16.row.col.f32.bf16.bf16.f32 "
        "{%0,%1,%2,%3}, {%4,%5,%6,%7}, {%8,%9}, {%0,%1,%2,%3};"
        : "+f"(c[0]), "+f"(c[1]), "+f"(c[2]), "+f"(c[3])
        : "r"(a[0]), "r"(a[1]), "r"(a[2]), "r"(a[3]), "r"(b0), "r"(b1));
}

// ===== fused prep: bf16 conversion + exact sequential sumsq for z AND codebook =====
__global__ void k_prep(const float* __restrict__ z, const float* __restrict__ cb, int n, int K) {
    int r = blockIdx.x * blockDim.x + threadIdx.x;
    const float* src;
    __nv_bfloat16* dst;
    float* outA;
    if (r < n) {
        src = z + (size_t)r * D;
        dst = g_zb + (size_t)r * D;
        outA = &g_A[r];
    } else if (r < n + K) {
        int c = r - n;
        src = cb + (size_t)c * D;
        dst = g_cbb + (size_t)c * D;
        outA = &g_C[c];
    } else return;

    const float4* p = reinterpret_cast<const float4*>(src);
    __nv_bfloat162* o = reinterpret_cast<__nv_bfloat162*>(dst);
    float a = 0.f;
#pragma unroll 8
    for (int i = 0; i < D / 4; ++i) {
        float4 v = p[i];
        a = __fadd_rn(a, __fmul_rn(v.x, v.x));
        a = __fadd_rn(a, __fmul_rn(v.y, v.y));
        a = __fadd_rn(a, __fmul_rn(v.z, v.z));
        a = __fadd_rn(a, __fmul_rn(v.w, v.w));
        o[i * 2]     = __floats2bfloat162_rn(v.x, v.y);
        o[i * 2 + 1] = __floats2bfloat162_rn(v.z, v.w);
    }
    *outA = a;
}

// ================= stage 1: HMMA bf16 GEMM + per-row candidates =================
// CTA: 128 rows x all K codes, chunks of 64 codes, 4 smem buffers, 1 sync/chunk.
// 512 threads = 16 warps (8M x 2N), warp tile 16 rows x 32 codes.
// A fragments live in registers (loaded once). smem rows padded to 528B.
#define PADB 528
#define CHUNK 64
#define SM_A   0
#define A_BYTES (128 * PADB)              // 67584
#define B_BYTES (CHUNK * PADB)            // 33792
#define SM_B(j) (A_BYTES + (j) * B_BYTES)
#define SM_TOT  (A_BYTES + 4 * B_BYTES)   // 202752

__global__ __launch_bounds__(512, 1)
void k_gemm_topk(int K) {
    extern __shared__ char sm[];
    const uint32_t sb = smem_u32(sm);
    const int tid = threadIdx.x;
    const int lid = tid & 31, wid = tid >> 5;
    const int warpM = wid >> 1, warpN = wid & 1;   // 8M x 2N
    const int g = lid >> 2, tg = lid & 3;
    const int row0 = blockIdx.x * 128;
    const int nchunks = K / CHUNK;   // 128

    // ---- issue A load (group 0) ----
    {
        const __nv_bfloat16* zsrc = g_zb + (size_t)row0 * D;
#pragma unroll
        for (int t = 0; t < 8; ++t) {
            int e = t * 512 + tid;          // 0..4095
            int r = e >> 5, j = e & 31;
            cpa16(sb + SM_A + r * PADB + j * 16, zsrc + (size_t)r * D + j * 8);
        }
        CP_COMMIT();
    }
    // ---- issue B chunks 0..2 (groups 1..3) ----
#pragma unroll
    for (int c = 0; c < 3; ++c) {
        const __nv_bfloat16* csrc = g_cbb + (size_t)c * CHUNK * D;
#pragma unroll
        for (int t = 0; t < 4; ++t) {
            int e = t * 512 + tid;          // 0..2047
            int r = e >> 5, j = e & 31;
            cpa16(sb + SM_B(c) + r * PADB + j * 16, csrc + (size_t)r * D + j * 8);
        }
        CP_COMMIT();
    }

    // wait for A (4 groups pending -> wait 3 completes group 0), then preload A regs
    CP_WAIT(3);
    __syncthreads();

    const int aLane = (lid & 15);
    const int aKoff = (lid >> 4) * 16;
    const uint32_t aBase = sb + SM_A + (uint32_t)(warpM * 16 + aLane) * PADB + aKoff;
    uint32_t aR[16][4];
#pragma unroll
    for (int ks = 0; ks < 16; ++ks) ldsm_x4(aR[ks], aBase + ks * 32);

    const int bCode = (lid & 7) + ((lid >> 4) << 3);
    const int bKoff = ((lid >> 3) & 1) * 16;
    const uint32_t bLaneOff = (uint32_t)(warpN * 32 + bCode) * PADB + bKoff;

    // per-thread top-2 for each of its 2 tracked rows (g, g+8)
    float bv[2][2];
    int   bi[2][2];
#pragma unroll
    for (int i = 0; i < 2; ++i) { bv[i][0] = bv[i][1] = -3.4e38f; bi[i][0] = bi[i][1] = 0; }

    for (int i = 0; i < nchunks; ++i) {
        // issue chunk i+3 (always commit to keep group accounting uniform)
        if (i + 3 < nchunks) {
            const __nv_bfloat16* csrc = g_cbb + (size_t)(i + 3) * CHUNK * D;
            const uint32_t dstb = sb + SM_B((i + 3) & 3);
#pragma unroll
            for (int t = 0; t < 4; ++t) {
                int e = t * 512 + tid;
                int r = e >> 5, j = e & 31;
                cpa16(dstb + r * PADB + j * 16, csrc + (size_t)r * D + j * 8);
            }
        }
        CP_COMMIT();
        CP_WAIT(3);          // chunk i's group complete
        __syncthreads();     // ... and visible to all threads; also closes WAR on buf (i+3)&3

        const uint32_t bufb = sb + SM_B(i & 3) + bLaneOff;

        float acc[4][4];
#pragma unroll
        for (int nt = 0; nt < 4; ++nt)
#pragma unroll
            for (int q = 0; q < 4; ++q) acc[nt][q] = 0.f;

#pragma unroll
        for (int ks = 0; ks < 16; ++ks) {
            uint32_t b0[4], b1[4];
            ldsm_x4(b0, bufb + ks * 32);                 // codes +0..15
            ldsm_x4(b1, bufb + 16 * PADB + ks * 32);     // codes +16..31
            mma_bf16(acc[0], aR[ks], b0[0], b0[1]);
            mma_bf16(acc[1], aR[ks], b0[2], b0[3]);
            mma_bf16(acc[2], aR[ks], b1[0], b1[1]);
            mma_bf16(acc[3], aR[ks], b1[2], b1[3]);
        }

        // ---- top-2 update (lazy index) ----
        const int cbase0 = i * CHUNK + warpN * 32 + tg * 2;
#pragma unroll
        for (int nt = 0; nt < 4; ++nt) {
#pragma unroll
            for (int q = 0; q < 4; ++q) {
                const int sl = q >> 1;                  // row slot: g / g+8
                const float v = acc[nt][q];
                if (v > bv[sl][1]) {
                    const int ci = cbase0 + nt * 8 + (q & 1);
                    if (v > bv[sl][0]) {
                        bv[sl][1] = bv[sl][0]; bi[sl][1] = bi[sl][0];
                        bv[sl][0] = v;         bi[sl][0] = ci;
                    } else {
                        bv[sl][1] = v;         bi[sl][1] = ci;
                    }
                }
            }
        }
    }

    // ---- merge: 8 owners x top2 per row -> global top4 ----
    __syncthreads();
    float* mv = reinterpret_cast<float*>(sm);           // 16*128 floats = 8KB
    int*   mi = reinterpret_cast<int*>(sm + 8192);      // 8KB
    const int owner = warpN * 4 + tg;                   // 0..7
#pragma unroll
    for (int sl = 0; sl < 2; ++sl) {
        const int srow = warpM * 16 + sl * 8 + g;
#pragma unroll
        for (int j = 0; j < 2; ++j) {
            mv[(owner * 2 + j) * 128 + srow] = bv[sl][j];
            mi[(owner * 2 + j) * 128 + srow] = bi[sl][j];
        }
    }
    __syncthreads();
    if (tid < 128) {
        float fv0=-3.4e38f, fv1=-3.4e38f, fv2=-3.4e38f, fv3=-3.4e38f;
        int   fi0=0, fi1=0, fi2=0, fi3=0;
#pragma unroll
        for (int e = 0; e < 16; ++e) {
            float v = mv[e * 128 + tid];
            if (v > fv3) {
                int ci = mi[e * 128 + tid];
                if (v > fv0)      { fv3=fv2;fi3=fi2; fv2=fv1;fi2=fi1; fv1=fv0;fi1=fi0; fv0=v;fi0=ci; }
                else if (v > fv1) { fv3=fv2;fi3=fi2; fv2=fv1;fi2=fi1; fv1=v;fi1=ci; }
                else if (v > fv2) { fv3=fv2;fi3=fi2; fv2=v;fi2=ci; }
                else              { fv3=v;fi3=ci; }
            }
        }
        const int r = row0 + tid;
        g_cand[r * 4 + 0] = fi0;
        g_cand[r * 4 + 1] = fi1;
        g_cand[r * 4 + 2] = fi2;
        g_cand[r * 4 + 3] = fi3;
    }
}

// ================= stage 2: exact fp32 rescore, 4 lanes per row =================
// Each lane: one candidate's sequential-k fmaf dot (identical order to the R1
// full scan), score = fl(fl(A-2B)+C); min-by-(value,index) via shfl butterfly.
__global__ void k_rescore(const float* __restrict__ z, const float* __restrict__ cb, int n) {
    int gid = blockIdx.x * blockDim.x + threadIdx.x;
    int row = gid >> 2, m = gid & 3;
    if (row >= n) return;
    const float4* zr = reinterpret_cast<const float4*>(z + (size_t)row * D);

    const float A = g_A[row];
    int c = g_cand[row * 4 + m];
    const float4* cr = reinterpret_cast<const float4*>(cb + (size_t)c * D);

    float acc = 0.f;
#pragma unroll 8
    for (int i = 0; i < D / 4; ++i) {
        float4 a = zr[i];
        float4 b = cr[i];
        acc = __fmaf_rn(a.x, b.x, acc);
        acc = __fmaf_rn(a.y, b.y, acc);
        acc = __fmaf_rn(a.z, b.z, acc);
        acc = __fmaf_rn(a.w, b.w, acc);
    }
    float s = __fadd_rn(__fmaf_rn(-2.f, acc, A), g_C[c]);

#pragma unroll
    for (int o = 1; o < 4; o <<= 1) {
        float sv = __shfl_xor_sync(0xffffffffu, s, o);
        int   ci = __shfl_xor_sync(0xffffffffu, c, o);
        if (sv < s || (sv == s && ci < c)) { s = sv; c = ci; }
    }
    if (m == 0) g_idx[row] = c;
}

// ================= finish: gather, z_q, per-row d^2, indices =================
__global__ void k_finish(const float* __restrict__ z, const float* __restrict__ cb,
                         float* __restrict__ zq, float* __restrict__ idxout) {
    const int row = blockIdx.x;
    const int t = threadIdx.x;          // 128 threads, 2 elems each
    const int code = g_idx[row];
    const float2 zp = reinterpret_cast<const float2*>(z + (size_t)row * D)[t];
    const float2 cp = reinterpret_cast<const float2*>(cb + (size_t)code * D)[t];
    float d0 = __fsub_rn(cp.x, zp.x);
    float d1 = __fsub_rn(cp.y, zp.y);
    float ss = __fadd_rn(__fmul_rn(d0, d0), __fmul_rn(d1, d1));

    __shared__ float red[4];
#pragma unroll
    for (int o = 16; o > 0; o >>= 1)
        ss = __fadd_rn(ss, __shfl_xor_sync(0xffffffffu, ss, o));
    if ((t & 31) == 0) red[t >> 5] = ss;
    __syncthreads();
    float ssum = __fadd_rn(__fadd_rn(red[0], red[1]), __fadd_rn(red[2], red[3]));

    float mag = __fsqrt_rn(ssum);
    float den = __fadd_rn(mag, 1e-8f);
    float q0 = __fadd_rn(zp.x, __fmul_rn(mag, __fdiv_rn(d0, den)));
    float q1 = __fadd_rn(zp.y, __fmul_rn(mag, __fdiv_rn(d1, den)));
    float2 o; o.x = q0; o.y = q1;
    reinterpret_cast<float2*>(zq + (size_t)row * D)[t] = o;
    if (t == 0) {
        g_rowss[row] = ssum;
        idxout[row] = (float)code;
    }
}

// ================= loss = 1.25 * mean(d^2) =================
__global__ void k_loss(float* __restrict__ out_loss, int n) {
    __shared__ double sred[256];
    double s = 0.0;
    for (int i = threadIdx.x; i < n; i += 256) s += (double)g_rowss[i];
    sred[threadIdx.x] = s;
    __syncthreads();
    for (int o = 128; o > 0; o >>= 1) {
        if (threadIdx.x < o) sred[threadIdx.x] += sred[threadIdx.x + o];
        __syncthreads();
    }
    if (threadIdx.x == 0) {
        double mean = sred[0] / ((double)n * (double)D);
        out_loss[0] = (float)(1.25 * mean);
    }
}

extern "C" void kernel_launch(void* const* d_in, const int* in_sizes, int n_in,
                              void* d_out, int out_size) {
    const float* z  = (const float*)d_in[0];
    const float* cb = (const float*)d_in[1];
    const int n = in_sizes[0] / D;   // 16384
    const int K = in_sizes[1] / D;   // 8192

    float* out    = (float*)d_out;
    float* zq     = out;
    float* loss   = out + (size_t)n * D;
    float* idxout = loss + 1;

    cudaFuncSetAttribute(k_gemm_topk, cudaFuncAttributeMaxDynamicSharedMemorySize, SM_TOT);

    k_prep<<<(n + K + 255) / 256, 256>>>(z, cb, n, K);
    k_gemm_topk<<<n / 128, 512, SM_TOT>>>(K);
    k_rescore<<<(n * 4 + 255) / 256, 256>>>(z, cb, n);
    k_finish<<<n, 128>>>(z, cb, zq, idxout);
    k_loss<<<1, 256>>>(loss, n);
}

// round 8
// speedup vs baseline: 1.5647x; 1.0601x over previous
#include <cuda_runtime.h>
#include <cuda_bf16.h>
#include <stdint.h>
#include <math.h>

#define D 256
#define MAXN 16384
#define MAXK 8192

// ---------------- scratch (module globals; no runtime allocation) ----------------
__device__ float          g_A[MAXN];          // per-row sum z^2 (exact sequential)
__device__ float          g_C[MAXK];          // per-code sum c^2
__device__ int            g_cand[MAXN * 4];   // top-4 candidates per row
__device__ int            g_idx[MAXN];        // final argmin per row
__device__ float          g_rowss[MAXN];      // per-row sum d^2
__device__ __nv_bfloat16  g_zb[MAXN * D];     // bf16 copy of z
__device__ __nv_bfloat16  g_cbb[MAXK * D];    // bf16 copy of codebook

// ================= tiny PTX helpers (all sm_80-legal) =================
__device__ __forceinline__ void cpa16(uint32_t dst, const void* src) {
    asm volatile("cp.async.cg.shared.global [%0], [%1], 16;" :: "r"(dst), "l"(src) : "memory");
}
#define CP_COMMIT() asm volatile("cp.async.commit_group;" ::: "memory")
#define CP_WAIT(n)  asm volatile("cp.async.wait_group %0;" :: "n"(n) : "memory")

__device__ __forceinline__ uint32_t smem_u32(const void* p) {
    uint32_t a;
    asm("{ .reg .u64 t; cvta.to.shared.u64 t, %1; cvt.u32.u64 %0, t; }" : "=r"(a) : "l"(p));
    return a;
}
__device__ __forceinline__ void ldsm_x4(uint32_t r[4], uint32_t addr) {
    asm volatile("ldmatrix.sync.aligned.m8n8.x4.shared.b16 {%0,%1,%2,%3}, [%4];"
        : "=r"(r[0]), "=r"(r[1]), "=r"(r[2]), "=r"(r[3]) : "r"(addr));
}
// D += A(16x16 bf16, row-major) * B(16x8 col-major)
__device__ __forceinline__ void mma_bf16(float c[4], const uint32_t a[4], uint32_t b0, uint32_t b1) {
    asm volatile(
        "mma.sync.aligned.m16n8k16.row.col.f32.bf16.bf16.f32 "
        "{%0,%1,%2,%3}, {%4,%5,%6,%7}, {%8,%9}, {%0,%1,%2,%3};"
        : "+f"(c[0]), "+f"(c[1]), "+f"(c[2]), "+f"(c[3])
        : "r"(a[0]), "r"(a[1]), "r"(a[2]), "r"(a[3]), "r"(b0), "r"(b1));
}

// ===== fused prep: bf16 conversion + exact sequential sumsq for z AND codebook =====
__global__ void k_prep(const float* __restrict__ z, const float* __restrict__ cb, int n, int K) {
    int r = blockIdx.x * blockDim.x + threadIdx.x;
    const float* src;
    __nv_bfloat16* dst;
    float* outA;
    if (r < n) {
        src = z + (size_t)r * D;
        dst = g_zb + (size_t)r * D;
        outA = &g_A[r];
    } else if (r < n + K) {
        int c = r - n;
        src = cb + (size_t)c * D;
        dst = g_cbb + (size_t)c * D;
        outA = &g_C[c];
    } else return;

    const float4* p = reinterpret_cast<const float4*>(src);
    __nv_bfloat162* o = reinterpret_cast<__nv_bfloat162*>(dst);
    float a = 0.f;
#pragma unroll 8
    for (int i = 0; i < D / 4; ++i) {
        float4 v = p[i];
        a = __fadd_rn(a, __fmul_rn(v.x, v.x));
        a = __fadd_rn(a, __fmul_rn(v.y, v.y));
        a = __fadd_rn(a, __fmul_rn(v.z, v.z));
        a = __fadd_rn(a, __fmul_rn(v.w, v.w));
        o[i * 2]     = __floats2bfloat162_rn(v.x, v.y);
        o[i * 2 + 1] = __floats2bfloat162_rn(v.z, v.w);
    }
    *outA = a;
}

// ================= stage 1: HMMA bf16 GEMM + per-row candidates =================
// CTA: 128 rows x all K codes, chunks of 128 codes, double-buffered.
// 256 threads = 8 warps (4M x 2N), warp tile 32 rows x 64 codes.
// Per k-step: 6 LDSM feed 16 independent MMAs. smem rows padded to 528B.
#define PADB 528
#define CHUNK 128
#define TILE_BYTES (128 * PADB)           // 67584 (A tile == B chunk size)
#define SM_A   0
#define SM_B(j) (TILE_BYTES + (j) * TILE_BYTES)
#define SM_TOT  (3 * TILE_BYTES)          // 202752

__global__ __launch_bounds__(256, 1)
void k_gemm_topk(int K) {
    extern __shared__ char sm[];
    const uint32_t sb = smem_u32(sm);
    const int tid = threadIdx.x;
    const int lid = tid & 31, wid = tid >> 5;
    const int warpM = wid >> 1, warpN = wid & 1;   // 4M x 2N
    const int g = lid >> 2, tg = lid & 3;
    const int row0 = blockIdx.x * 128;
    const int nchunks = K / CHUNK;   // 64

    // ---- load A (128 rows x 256 bf16): 4096 16B-chunks / 256 threads ----
    {
        const __nv_bfloat16* zsrc = g_zb + (size_t)row0 * D;
#pragma unroll
        for (int t = 0; t < 16; ++t) {
            int e = t * 256 + tid;
            int r = e >> 5, j = e & 31;
            cpa16(sb + SM_A + r * PADB + j * 16, zsrc + (size_t)r * D + j * 8);
        }
        CP_COMMIT();
    }
    // ---- prefetch B chunk 0 ----
    {
#pragma unroll
        for (int t = 0; t < 16; ++t) {
            int e = t * 256 + tid;
            int r = e >> 5, j = e & 31;
            cpa16(sb + SM_B(0) + r * PADB + j * 16, g_cbb + (size_t)r * D + j * 8);
        }
        CP_COMMIT();
    }

    // ldmatrix lane address components
    const int aLane = (lid & 15);
    const int aKoff = (lid >> 4) * 16;
    uint32_t aAddr[2];
#pragma unroll
    for (int mt = 0; mt < 2; ++mt)
        aAddr[mt] = sb + SM_A + (uint32_t)(warpM * 32 + mt * 16 + aLane) * PADB + aKoff;

    const int bCode = (lid & 7) + ((lid >> 4) << 3);
    const int bKoff = ((lid >> 3) & 1) * 16;
    const uint32_t bLaneOff = (uint32_t)(warpN * 64 + bCode) * PADB + bKoff;

    // per-thread top-2 for each of its 4 tracked rows
    float bv[4][2];
    int   bi[4][2];
#pragma unroll
    for (int i = 0; i < 4; ++i) { bv[i][0] = bv[i][1] = -3.4e38f; bi[i][0] = bi[i][1] = 0; }

    for (int i = 0; i < nchunks; ++i) {
        const int s = i & 1;
        if (i + 1 < nchunks) {
            const __nv_bfloat16* csrc = g_cbb + (size_t)(i + 1) * CHUNK * D;
            const uint32_t dstb = sb + SM_B(1 - s);
#pragma unroll
            for (int t = 0; t < 16; ++t) {
                int e = t * 256 + tid;
                int r = e >> 5, j = e & 31;
                cpa16(dstb + r * PADB + j * 16, csrc + (size_t)r * D + j * 8);
            }
            CP_COMMIT();
            CP_WAIT(1);
        } else {
            CP_WAIT(0);
        }
        __syncthreads();

        const uint32_t bufb = sb + SM_B(s) + bLaneOff;

        float acc[2][8][4];
#pragma unroll
        for (int mt = 0; mt < 2; ++mt)
#pragma unroll
            for (int nt = 0; nt < 8; ++nt)
#pragma unroll
                for (int q = 0; q < 4; ++q) acc[mt][nt][q] = 0.f;

#pragma unroll
        for (int ks = 0; ks < 16; ++ks) {
            uint32_t a[2][4];
            ldsm_x4(a[0], aAddr[0] + ks * 32);
            ldsm_x4(a[1], aAddr[1] + ks * 32);
#pragma unroll
            for (int p = 0; p < 4; ++p) {
                uint32_t b[4];
                ldsm_x4(b, bufb + (uint32_t)(p * 16) * PADB + ks * 32);
                mma_bf16(acc[0][2 * p],     a[0], b[0], b[1]);
                mma_bf16(acc[1][2 * p],     a[1], b[0], b[1]);
                mma_bf16(acc[0][2 * p + 1], a[0], b[2], b[3]);
                mma_bf16(acc[1][2 * p + 1], a[1], b[2], b[3]);
            }
        }

        // ---- top-2 update (lazy index) ----
        const int cbase0 = i * CHUNK + warpN * 64 + tg * 2;
#pragma unroll
        for (int mt = 0; mt < 2; ++mt) {
#pragma unroll
            for (int nt = 0; nt < 8; ++nt) {
#pragma unroll
                for (int q = 0; q < 4; ++q) {
                    const int sl = mt * 2 + (q >> 1);
                    const float v = acc[mt][nt][q];
                    if (v > bv[sl][1]) {
                        const int ci = cbase0 + nt * 8 + (q & 1);
                        if (v > bv[sl][0]) {
                            bv[sl][1] = bv[sl][0]; bi[sl][1] = bi[sl][0];
                            bv[sl][0] = v;         bi[sl][0] = ci;
                        } else {
                            bv[sl][1] = v;         bi[sl][1] = ci;
                        }
                    }
                }
            }
        }
        __syncthreads();
    }

    // ---- merge: 8 owners x top2 per row -> global top4 ----
    float* mv = reinterpret_cast<float*>(sm);           // 16*128 floats = 8KB
    int*   mi = reinterpret_cast<int*>(sm + 8192);      // 8KB
    const int owner = warpN * 4 + tg;                   // 0..7
#pragma unroll
    for (int sl = 0; sl < 4; ++sl) {
        const int srow = warpM * 32 + (sl >> 1) * 16 + (sl & 1) * 8 + g;
#pragma unroll
        for (int j = 0; j < 2; ++j) {
            mv[(owner * 2 + j) * 128 + srow] = bv[sl][j];
            mi[(owner * 2 + j) * 128 + srow] = bi[sl][j];
        }
    }
    __syncthreads();
    if (tid < 128) {
        float fv0=-3.4e38f, fv1=-3.4e38f, fv2=-3.4e38f, fv3=-3.4e38f;
        int   fi0=0, fi1=0, fi2=0, fi3=0;
#pragma unroll
        for (int e = 0; e < 16; ++e) {
            float v = mv[e * 128 + tid];
            if (v > fv3) {
                int ci = mi[e * 128 + tid];
                if (v > fv0)      { fv3=fv2;fi3=fi2; fv2=fv1;fi2=fi1; fv1=fv0;fi1=fi0; fv0=v;fi0=ci; }
                else if (v > fv1) { fv3=fv2;fi3=fi2; fv2=fv1;fi2=fi1; fv1=v;fi1=ci; }
                else if (v > fv2) { fv3=fv2;fi3=fi2; fv2=v;fi2=ci; }
                else              { fv3=v;fi3=ci; }
            }
        }
        const int r = row0 + tid;
        g_cand[r * 4 + 0] = fi0;
        g_cand[r * 4 + 1] = fi1;
        g_cand[r * 4 + 2] = fi2;
        g_cand[r * 4 + 3] = fi3;
    }
}

// ================= stage 2: exact fp32 rescore, 4 lanes per row =================
// Each lane: one candidate's sequential-k fmaf dot (identical order to the R1
// full scan), score = fl(fl(A-2B)+C); min-by-(value,index) via shfl butterfly.
__global__ void k_rescore(const float* __restrict__ z, const float* __restrict__ cb, int n) {
    int gid = blockIdx.x * blockDim.x + threadIdx.x;
    int row = gid >> 2, m = gid & 3;
    if (row >= n) return;
    const float4* zr = reinterpret_cast<const float4*>(z + (size_t)row * D);

    const float A = g_A[row];
    int c = g_cand[row * 4 + m];
    const float4* cr = reinterpret_cast<const float4*>(cb + (size_t)c * D);

    float acc = 0.f;
#pragma unroll 8
    for (int i = 0; i < D / 4; ++i) {
        float4 a = zr[i];
        float4 b = cr[i];
        acc = __fmaf_rn(a.x, b.x, acc);
        acc = __fmaf_rn(a.y, b.y, acc);
        acc = __fmaf_rn(a.z, b.z, acc);
        acc = __fmaf_rn(a.w, b.w, acc);
    }
    float s = __fadd_rn(__fmaf_rn(-2.f, acc, A), g_C[c]);

#pragma unroll
    for (int o = 1; o < 4; o <<= 1) {
        float sv = __shfl_xor_sync(0xffffffffu, s, o);
        int   ci = __shfl_xor_sync(0xffffffffu, c, o);
        if (sv < s || (sv == s && ci < c)) { s = sv; c = ci; }
    }
    if (m == 0) g_idx[row] = c;
}

// ================= finish: gather, z_q, per-row d^2, indices =================
__global__ void k_finish(const float* __restrict__ z, const float* __restrict__ cb,
                         float* __restrict__ zq, float* __restrict__ idxout) {
    const int row = blockIdx.x;
    const int t = threadIdx.x;          // 128 threads, 2 elems each
    const int code = g_idx[row];
    const float2 zp = reinterpret_cast<const float2*>(z + (size_t)row * D)[t];
    const float2 cp = reinterpret_cast<const float2*>(cb + (size_t)code * D)[t];
    float d0 = __fsub_rn(cp.x, zp.x);
    float d1 = __fsub_rn(cp.y, zp.y);
    float ss = __fadd_rn(__fmul_rn(d0, d0), __fmul_rn(d1, d1));

    __shared__ float red[4];
#pragma unroll
    for (int o = 16; o > 0; o >>= 1)
        ss = __fadd_rn(ss, __shfl_xor_sync(0xffffffffu, ss, o));
    if ((t & 31) == 0) red[t >> 5] = ss;
    __syncthreads();
    float ssum = __fadd_rn(__fadd_rn(red[0], red[1]), __fadd_rn(red[2], red[3]));

    float mag = __fsqrt_rn(ssum);
    float den = __fadd_rn(mag, 1e-8f);
    float q0 = __fadd_rn(zp.x, __fmul_rn(mag, __fdiv_rn(d0, den)));
    float q1 = __fadd_rn(zp.y, __fmul_rn(mag, __fdiv_rn(d1, den)));
    float2 o; o.x = q0; o.y = q1;
    reinterpret_cast<float2*>(zq + (size_t)row * D)[t] = o;
    if (t == 0) {
        g_rowss[row] = ssum;
        idxout[row] = (float)code;
    }
}

// ================= loss = 1.25 * mean(d^2) =================
__global__ void k_loss(float* __restrict__ out_loss, int n) {
    __shared__ double sred[256];
    double s = 0.0;
    for (int i = threadIdx.x; i < n; i += 256) s += (double)g_rowss[i];
    sred[threadIdx.x] = s;
    __syncthreads();
    for (int o = 128; o > 0; o >>= 1) {
        if (threadIdx.x < o) sred[threadIdx.x] += sred[threadIdx.x + o];
        __syncthreads();
    }
    if (threadIdx.x == 0) {
        double mean = sred[0] / ((double)n * (double)D);
        out_loss[0] = (float)(1.25 * mean);
    }
}

extern "C" void kernel_launch(void* const* d_in, const int* in_sizes, int n_in,
                              void* d_out, int out_size) {
    const float* z  = (const float*)d_in[0];
    const float* cb = (const float*)d_in[1];
    const int n = in_sizes[0] / D;   // 16384
    const int K = in_sizes[1] / D;   // 8192

    float* out    = (float*)d_out;
    float* zq     = out;
    float* loss   = out + (size_t)n * D;
    float* idxout = loss + 1;

    cudaFuncSetAttribute(k_gemm_topk, cudaFuncAttributeMaxDynamicSharedMemorySize, SM_TOT);

    k_prep<<<(n + K + 255) / 256, 256>>>(z, cb, n, K);
    k_gemm_topk<<<n / 128, 256, SM_TOT>>>(K);
    k_rescore<<<(n * 4 + 255) / 256, 256>>>(z, cb, n);
    k_finish<<<n, 128>>>(z, cb, zq, idxout);
    k_loss<<<1, 256>>>(loss, n);
}

// round 9
// speedup vs baseline: 1.6103x; 1.0291x over previous
#include <cuda_runtime.h>
#include <cuda_bf16.h>
#include <stdint.h>
#include <math.h>

#define D 256
#define MAXN 16384
#define MAXK 8192

// ---------------- scratch (module globals; no runtime allocation) ----------------
__device__ float          g_A[MAXN];          // per-row sum z^2 (exact sequential)
__device__ float          g_C[MAXK];          // per-code sum c^2
__device__ int            g_cand[MAXN * 8];   // top-4 per row per K-half
__device__ int            g_idx[MAXN];        // final argmin per row
__device__ float          g_rowss[MAXN];      // per-row sum d^2
__device__ __nv_bfloat16  g_zb[MAXN * D];     // bf16 copy of z
__device__ __nv_bfloat16  g_cbb[MAXK * D];    // bf16 copy of codebook

// ================= tiny PTX helpers (all sm_80-legal) =================
__device__ __forceinline__ void cpa16(uint32_t dst, const void* src) {
    asm volatile("cp.async.cg.shared.global [%0], [%1], 16;" :: "r"(dst), "l"(src) : "memory");
}
#define CP_COMMIT() asm volatile("cp.async.commit_group;" ::: "memory")
#define CP_WAIT(n)  asm volatile("cp.async.wait_group %0;" :: "n"(n) : "memory")

__device__ __forceinline__ uint32_t smem_u32(const void* p) {
    uint32_t a;
    asm("{ .reg .u64 t; cvta.to.shared.u64 t, %1; cvt.u32.u64 %0, t; }" : "=r"(a) : "l"(p));
    return a;
}
__device__ __forceinline__ void ldsm_x4(uint32_t r[4], uint32_t addr) {
    asm volatile("ldmatrix.sync.aligned.m8n8.x4.shared.b16 {%0,%1,%2,%3}, [%4];"
        : "=r"(r[0]), "=r"(r[1]), "=r"(r[2]), "=r"(r[3]) : "r"(addr));
}
// D += A(16x16 bf16, row-major) * B(16x8 col-major)
__device__ __forceinline__ void mma_bf16(float c[4], const uint32_t a[4], uint32_t b0, uint32_t b1) {
    asm volatile(
        "mma.sync.aligned.m16n8k16.row.col.f32.bf16.bf16.f32 "
        "{%0,%1,%2,%3}, {%4,%5,%6,%7}, {%8,%9}, {%0,%1,%2,%3};"
        : "+f"(c[0]), "+f"(c[1]), "+f"(c[2]), "+f"(c[3])
        : "r"(a[0]), "r"(a[1]), "r"(a[2]), "r"(a[3]), "r"(b0), "r"(b1));
}

// ===== fused prep: bf16 conversion + exact sequential sumsq for z AND codebook =====
__global__ void k_prep(const float* __restrict__ z, const float* __restrict__ cb, int n, int K) {
    int r = blockIdx.x * blockDim.x + threadIdx.x;
    const float* src;
    __nv_bfloat16* dst;
    float* outA;
    if (r < n) {
        src = z + (size_t)r * D;
        dst = g_zb + (size_t)r * D;
        outA = &g_A[r];
    } else if (r < n + K) {
        int c = r - n;
        src = cb + (size_t)c * D;
        dst = g_cbb + (size_t)c * D;
        outA = &g_C[c];
    } else return;

    const float4* p = reinterpret_cast<const float4*>(src);
    __nv_bfloat162* o = reinterpret_cast<__nv_bfloat162*>(dst);
    float a = 0.f;
#pragma unroll 8
    for (int i = 0; i < D / 4; ++i) {
        float4 v = p[i];
        a = __fadd_rn(a, __fmul_rn(v.x, v.x));
        a = __fadd_rn(a, __fmul_rn(v.y, v.y));
        a = __fadd_rn(a, __fmul_rn(v.z, v.z));
        a = __fadd_rn(a, __fmul_rn(v.w, v.w));
        o[i * 2]     = __floats2bfloat162_rn(v.x, v.y);
        o[i * 2 + 1] = __floats2bfloat162_rn(v.z, v.w);
    }
    *outA = a;
}

// ================= stage 1: HMMA bf16 GEMM + per-row candidates =================
// Grid: 128 row-tiles x 2 K-halves. CTA: 128 rows x 4096 codes, chunks of 32 codes,
// double-buffered smem (B only). 256 threads = 8 warps (8M), warp tile 16 x 32.
// A fragments live in registers, loaded once from global. smem rows padded to 528B.
#define PADB 528
#define CHUNK 32
#define B_BYTES (CHUNK * PADB)            // 16896
#define SM_B(j) ((j) * B_BYTES)
#define SM_TOT  (2 * B_BYTES)             // 33792

__global__ __launch_bounds__(256, 2)
void k_gemm_topk(int K) {
    extern __shared__ char sm[];
    const uint32_t sb = smem_u32(sm);
    const int tid = threadIdx.x;
    const int lid = tid & 31, wid = tid >> 5;     // wid = warpM (8M x 1N)
    const int g = lid >> 2, tg = lid & 3;
    const int tile = blockIdx.x >> 1;
    const int half = blockIdx.x & 1;
    const int row0 = tile * 128;
    const int code0 = half * (K >> 1);
    const int nchunks = (K >> 1) / CHUNK;         // 128

    // ---- prefetch B chunk 0 ----
    {
        const __nv_bfloat16* csrc = g_cbb + (size_t)code0 * D;
#pragma unroll
        for (int t = 0; t < 4; ++t) {
            int e = t * 256 + tid;
            int r = e >> 5, j = e & 31;
            cpa16(sb + SM_B(0) + r * PADB + j * 16, csrc + (size_t)r * D + j * 8);
        }
        CP_COMMIT();
    }

    // ---- load A fragments straight from global into registers (one-time) ----
    // m16n8k16 A layout: a0=A[g][k0+tg*2..], a1=A[g+8][..], a2=A[g][k0+8+..], a3=A[g+8][..]
    uint32_t aR[16][4];
    {
        const uint32_t* w = reinterpret_cast<const uint32_t*>(g_zb);
        const uint32_t rA = (uint32_t)(row0 + wid * 16 + g) * 128u;
        const uint32_t rB = rA + 8u * 128u;
#pragma unroll
        for (int ks = 0; ks < 16; ++ks) {
            aR[ks][0] = __ldg(w + rA + ks * 8 + tg);
            aR[ks][1] = __ldg(w + rB + ks * 8 + tg);
            aR[ks][2] = __ldg(w + rA + ks * 8 + 4 + tg);
            aR[ks][3] = __ldg(w + rB + ks * 8 + 4 + tg);
        }
    }

    const int bCode = (lid & 7) + ((lid >> 4) << 3);
    const int bKoff = ((lid >> 3) & 1) * 16;
    const uint32_t bLaneOff = (uint32_t)bCode * PADB + bKoff;

    // per-thread top-2 for each of its 2 tracked rows (g, g+8)
    float bv[2][2];
    int   bi[2][2];
#pragma unroll
    for (int i = 0; i < 2; ++i) { bv[i][0] = bv[i][1] = -3.4e38f; bi[i][0] = bi[i][1] = 0; }

    for (int i = 0; i < nchunks; ++i) {
        const int s = i & 1;
        if (i + 1 < nchunks) {
            const __nv_bfloat16* csrc = g_cbb + (size_t)(code0 + (i + 1) * CHUNK) * D;
            const uint32_t dstb = sb + SM_B(1 - s);
#pragma unroll
            for (int t = 0; t < 4; ++t) {
                int e = t * 256 + tid;
                int r = e >> 5, j = e & 31;
                cpa16(dstb + r * PADB + j * 16, csrc + (size_t)r * D + j * 8);
            }
            CP_COMMIT();
            CP_WAIT(1);
        } else {
            CP_WAIT(0);
        }
        __syncthreads();

        const uint32_t bufb = sb + SM_B(s) + bLaneOff;

        float acc[4][4];
#pragma unroll
        for (int nt = 0; nt < 4; ++nt)
#pragma unroll
            for (int q = 0; q < 4; ++q) acc[nt][q] = 0.f;

#pragma unroll
        for (int ks = 0; ks < 16; ++ks) {
            uint32_t b0[4], b1[4];
            ldsm_x4(b0, bufb + ks * 32);                 // codes +0..15
            ldsm_x4(b1, bufb + 16 * PADB + ks * 32);     // codes +16..31
            mma_bf16(acc[0], aR[ks], b0[0], b0[1]);
            mma_bf16(acc[1], aR[ks], b0[2], b0[3]);
            mma_bf16(acc[2], aR[ks], b1[0], b1[1]);
            mma_bf16(acc[3], aR[ks], b1[2], b1[3]);
        }

        // ---- top-2 update (lazy index) ----
        const int cbase0 = code0 + i * CHUNK + tg * 2;
#pragma unroll
        for (int nt = 0; nt < 4; ++nt) {
#pragma unroll
            for (int q = 0; q < 4; ++q) {
                const int sl = q >> 1;                   // row slot: g / g+8
                const float v = acc[nt][q];
                if (v > bv[sl][1]) {
                    const int ci = cbase0 + nt * 8 + (q & 1);
                    if (v > bv[sl][0]) {
                        bv[sl][1] = bv[sl][0]; bi[sl][1] = bi[sl][0];
                        bv[sl][0] = v;         bi[sl][0] = ci;
                    } else {
                        bv[sl][1] = v;         bi[sl][1] = ci;
                    }
                }
            }
        }
        __syncthreads();
    }

    // ---- merge: 4 owners x top2 per row -> top4 for this half ----
    float* mv = reinterpret_cast<float*>(sm);           // 8*128 floats = 4KB
    int*   mi = reinterpret_cast<int*>(sm + 4096);      // 4KB
#pragma unroll
    for (int sl = 0; sl < 2; ++sl) {
        const int srow = wid * 16 + sl * 8 + g;
#pragma unroll
        for (int j = 0; j < 2; ++j) {
            mv[(tg * 2 + j) * 128 + srow] = bv[sl][j];
            mi[(tg * 2 + j) * 128 + srow] = bi[sl][j];
        }
    }
    __syncthreads();
    if (tid < 128) {
        float fv0=-3.4e38f, fv1=-3.4e38f, fv2=-3.4e38f, fv3=-3.4e38f;
        int   fi0=0, fi1=0, fi2=0, fi3=0;
#pragma unroll
        for (int e = 0; e < 8; ++e) {
            float v = mv[e * 128 + tid];
            if (v > fv3) {
                int ci = mi[e * 128 + tid];
                if (v > fv0)      { fv3=fv2;fi3=fi2; fv2=fv1;fi2=fi1; fv1=fv0;fi1=fi0; fv0=v;fi0=ci; }
                else if (v > fv1) { fv3=fv2;fi3=fi2; fv2=fv1;fi2=fi1; fv1=v;fi1=ci; }
                else if (v > fv2) { fv3=fv2;fi3=fi2; fv2=v;fi2=ci; }
                else              { fv3=v;fi3=ci; }
            }
        }
        const int r = row0 + tid;
        g_cand[r * 8 + half * 4 + 0] = fi0;
        g_cand[r * 8 + half * 4 + 1] = fi1;
        g_cand[r * 8 + half * 4 + 2] = fi2;
        g_cand[r * 8 + half * 4 + 3] = fi3;
    }
}

// ================= stage 2: exact fp32 rescore, 8 lanes per row =================
// Each lane: one candidate's sequential-k fmaf dot (identical order to the R1
// full scan), score = fl(fl(A-2B)+C); min-by-(value,index) via shfl butterfly.
__global__ void k_rescore(const float* __restrict__ z, const float* __restrict__ cb, int n) {
    int gid = blockIdx.x * blockDim.x + threadIdx.x;
    int row = gid >> 3, m = gid & 7;
    if (row >= n) return;
    const float4* zr = reinterpret_cast<const float4*>(z + (size_t)row * D);

    const float A = g_A[row];
    int c = g_cand[row * 8 + m];
    const float4* cr = reinterpret_cast<const float4*>(cb + (size_t)c * D);

    float acc = 0.f;
#pragma unroll 8
    for (int i = 0; i < D / 4; ++i) {
        float4 a = zr[i];
        float4 b = cr[i];
        acc = __fmaf_rn(a.x, b.x, acc);
        acc = __fmaf_rn(a.y, b.y, acc);
        acc = __fmaf_rn(a.z, b.z, acc);
        acc = __fmaf_rn(a.w, b.w, acc);
    }
    float s = __fadd_rn(__fmaf_rn(-2.f, acc, A), g_C[c]);

#pragma unroll
    for (int o = 1; o < 8; o <<= 1) {
        float sv = __shfl_xor_sync(0xffffffffu, s, o);
        int   ci = __shfl_xor_sync(0xffffffffu, c, o);
        if (sv < s || (sv == s && ci < c)) { s = sv; c = ci; }
    }
    if (m == 0) g_idx[row] = c;
}

// ================= finish: gather, z_q, per-row d^2, indices =================
__global__ void k_finish(const float* __restrict__ z, const float* __restrict__ cb,
                         float* __restrict__ zq, float* __restrict__ idxout) {
    const int row = blockIdx.x;
    const int t = threadIdx.x;          // 128 threads, 2 elems each
    const int code = g_idx[row];
    const float2 zp = reinterpret_cast<const float2*>(z + (size_t)row * D)[t];
    const float2 cp = reinterpret_cast<const float2*>(cb + (size_t)code * D)[t];
    float d0 = __fsub_rn(cp.x, zp.x);
    float d1 = __fsub_rn(cp.y, zp.y);
    float ss = __fadd_rn(__fmul_rn(d0, d0), __fmul_rn(d1, d1));

    __shared__ float red[4];
#pragma unroll
    for (int o = 16; o > 0; o >>= 1)
        ss = __fadd_rn(ss, __shfl_xor_sync(0xffffffffu, ss, o));
    if ((t & 31) == 0) red[t >> 5] = ss;
    __syncthreads();
    float ssum = __fadd_rn(__fadd_rn(red[0], red[1]), __fadd_rn(red[2], red[3]));

    float mag = __fsqrt_rn(ssum);
    float den = __fadd_rn(mag, 1e-8f);
    float q0 = __fadd_rn(zp.x, __fmul_rn(mag, __fdiv_rn(d0, den)));
    float q1 = __fadd_rn(zp.y, __fmul_rn(mag, __fdiv_rn(d1, den)));
    float2 o; o.x = q0; o.y = q1;
    reinterpret_cast<float2*>(zq + (size_t)row * D)[t] = o;
    if (t == 0) {
        g_rowss[row] = ssum;
        idxout[row] = (float)code;
    }
}

// ================= loss = 1.25 * mean(d^2) =================
__global__ void k_loss(float* __restrict__ out_loss, int n) {
    __shared__ double sred[256];
    double s = 0.0;
    for (int i = threadIdx.x; i < n; i += 256) s += (double)g_rowss[i];
    sred[threadIdx.x] = s;
    __syncthreads();
    for (int o = 128; o > 0; o >>= 1) {
        if (threadIdx.x < o) sred[threadIdx.x] += sred[threadIdx.x + o];
        __syncthreads();
    }
    if (threadIdx.x == 0) {
        double mean = sred[0] / ((double)n * (double)D);
        out_loss[0] = (float)(1.25 * mean);
    }
}

extern "C" void kernel_launch(void* const* d_in, const int* in_sizes, int n_in,
                              void* d_out, int out_size) {
    const float* z  = (const float*)d_in[0];
    const float* cb = (const float*)d_in[1];
    const int n = in_sizes[0] / D;   // 16384
    const int K = in_sizes[1] / D;   // 8192

    float* out    = (float*)d_out;
    float* zq     = out;
    float* loss   = out + (size_t)n * D;
    float* idxout = loss + 1;

    cudaFuncSetAttribute(k_gemm_topk, cudaFuncAttributeMaxDynamicSharedMemorySize, SM_TOT);

    k_prep<<<(n + K + 255) / 256, 256>>>(z, cb, n, K);
    k_gemm_topk<<<(n / 128) * 2, 256, SM_TOT>>>(K);
    k_rescore<<<(n * 8 + 255) / 256, 256>>>(z, cb, n);
    k_finish<<<n, 128>>>(z, cb, zq, idxout);
    k_loss<<<1, 256>>>(loss, n);
}

// round 10
// speedup vs baseline: 1.6439x; 1.0208x over previous
#include <cuda_runtime.h>
#include <cuda_bf16.h>
#include <stdint.h>
#include <math.h>

#define D 256
#define MAXN 16384
#define MAXK 8192

// ---------------- scratch (module globals; no runtime allocation) ----------------
__device__ float          g_C[MAXK];          // per-code sum c^2 (exact sequential)
__device__ int            g_cand[MAXN * 4];   // top-4 candidates per row
__device__ int            g_idx[MAXN];        // final argmin per row
__device__ float          g_rowss[MAXN];      // per-row sum d^2
__device__ __nv_bfloat16  g_zb[MAXN * D];     // bf16 copy of z
__device__ __nv_bfloat16  g_cbb[MAXK * D];    // bf16 copy of codebook

// ================= tiny PTX helpers (all sm_80-legal) =================
__device__ __forceinline__ void cpa16(uint32_t dst, const void* src) {
    asm volatile("cp.async.cg.shared.global [%0], [%1], 16;" :: "r"(dst), "l"(src) : "memory");
}
#define CP_COMMIT() asm volatile("cp.async.commit_group;" ::: "memory")
#define CP_WAIT(n)  asm volatile("cp.async.wait_group %0;" :: "n"(n) : "memory")

__device__ __forceinline__ uint32_t smem_u32(const void* p) {
    uint32_t a;
    asm("{ .reg .u64 t; cvta.to.shared.u64 t, %1; cvt.u32.u64 %0, t; }" : "=r"(a) : "l"(p));
    return a;
}
__device__ __forceinline__ void ldsm_x4(uint32_t r[4], uint32_t addr) {
    asm volatile("ldmatrix.sync.aligned.m8n8.x4.shared.b16 {%0,%1,%2,%3}, [%4];"
        : "=r"(r[0]), "=r"(r[1]), "=r"(r[2]), "=r"(r[3]) : "r"(addr));
}
// D += A(16x16 bf16, row-major) * B(16x8 col-major)
__device__ __forceinline__ void mma_bf16(float c[4], const uint32_t a[4], uint32_t b0, uint32_t b1) {
    asm volatile(
        "mma.sync.aligned.m16n8k16.row.col.f32.bf16.bf16.f32 "
        "{%0,%1,%2,%3}, {%4,%5,%6,%7}, {%8,%9}, {%0,%1,%2,%3};"
        : "+f"(c[0]), "+f"(c[1]), "+f"(c[2]), "+f"(c[3])
        : "r"(a[0]), "r"(a[1]), "r"(a[2]), "r"(a[3]), "r"(b0), "r"(b1));
}

// ===== flat element-parallel f32 -> bf16 conversion (both arrays) =====
__global__ void k_cvt(const float* __restrict__ z, const float* __restrict__ cb,
                      int nz4, int nc4) {
    int i = blockIdx.x * blockDim.x + threadIdx.x;
    const float4* src;
    __nv_bfloat162* dst;
    int j;
    if (i < nz4) {
        src = reinterpret_cast<const float4*>(z);
        dst = reinterpret_cast<__nv_bfloat162*>(g_zb);
        j = i;
    } else if (i < nz4 + nc4) {
        src = reinterpret_cast<const float4*>(cb);
        dst = reinterpret_cast<__nv_bfloat162*>(g_cbb);
        j = i - nz4;
    } else return;
    float4 v = src[j];
    dst[j * 2]     = __floats2bfloat162_rn(v.x, v.y);
    dst[j * 2 + 1] = __floats2bfloat162_rn(v.z, v.w);
}

// ===== codebook sumsq (exact sequential order, matches R1) =====
__global__ void k_sumsq_cb(const float* __restrict__ cb, int K) {
    int r = blockIdx.x * blockDim.x + threadIdx.x;
    if (r >= K) return;
    const float4* p = reinterpret_cast<const float4*>(cb + (size_t)r * D);
    float a = 0.f;
#pragma unroll 8
    for (int i = 0; i < D / 4; ++i) {
        float4 v = p[i];
        a = __fadd_rn(a, __fmul_rn(v.x, v.x));
        a = __fadd_rn(a, __fmul_rn(v.y, v.y));
        a = __fadd_rn(a, __fmul_rn(v.z, v.z));
        a = __fadd_rn(a, __fmul_rn(v.w, v.w));
    }
    g_C[r] = a;
}

// ================= stage 1: HMMA bf16 GEMM + per-row candidates =================
// Grid: 128 CTAs (one per 128-row tile). CTA: 256 threads = 8 warps (4M x 2N),
// warp tile 32 rows x 32 codes, chunks of 64 codes double-buffered (B-only smem).
// A fragments live in 128 registers/thread, loaded once from global.
#define PADB 528
#define CHUNK 64
#define B_BYTES (CHUNK * PADB)            // 33792
#define SM_B(j) ((j) * B_BYTES)
#define SM_TOT  (2 * B_BYTES)             // 67584

__global__ __launch_bounds__(256, 1)
void k_gemm_topk(int K) {
    extern __shared__ char sm[];
    const uint32_t sb = smem_u32(sm);
    const int tid = threadIdx.x;
    const int lid = tid & 31, wid = tid >> 5;
    const int warpM = wid >> 1, warpN = wid & 1;  // 4M x 2N
    const int g = lid >> 2, tg = lid & 3;
    const int row0 = blockIdx.x * 128;
    const int nchunks = K / CHUNK;                // 128

    // ---- prefetch B chunk 0 ----
    {
#pragma unroll
        for (int t = 0; t < 8; ++t) {
            int e = t * 256 + tid;               // 0..2047
            int r = e >> 5, j = e & 31;
            cpa16(sb + SM_B(0) + r * PADB + j * 16, g_cbb + (size_t)r * D + j * 8);
        }
        CP_COMMIT();
    }

    // ---- load A fragments straight from global into registers (one-time) ----
    // warp covers rows [warpM*32, warpM*32+32): two m16 groups (mt=0,1)
    uint32_t aR[2][16][4];
    {
        const uint32_t* w = reinterpret_cast<const uint32_t*>(g_zb);
#pragma unroll
        for (int mt = 0; mt < 2; ++mt) {
            const uint32_t rA = (uint32_t)(row0 + warpM * 32 + mt * 16 + g) * 128u;
            const uint32_t rB = rA + 8u * 128u;
#pragma unroll
            for (int ks = 0; ks < 16; ++ks) {
                aR[mt][ks][0] = __ldg(w + rA + ks * 8 + tg);
                aR[mt][ks][1] = __ldg(w + rB + ks * 8 + tg);
                aR[mt][ks][2] = __ldg(w + rA + ks * 8 + 4 + tg);
                aR[mt][ks][3] = __ldg(w + rB + ks * 8 + 4 + tg);
            }
        }
    }

    const int bCode = (lid & 7) + ((lid >> 4) << 3);
    const int bKoff = ((lid >> 3) & 1) * 16;
    const uint32_t bLaneOff = (uint32_t)(warpN * 32 + bCode) * PADB + bKoff;

    // per-thread top-2 for each of its 4 tracked rows
    float bv[4][2];
    int   bi[4][2];
#pragma unroll
    for (int i = 0; i < 4; ++i) { bv[i][0] = bv[i][1] = -3.4e38f; bi[i][0] = bi[i][1] = 0; }

    for (int i = 0; i < nchunks; ++i) {
        const int s = i & 1;
        if (i + 1 < nchunks) {
            const __nv_bfloat16* csrc = g_cbb + (size_t)(i + 1) * CHUNK * D;
            const uint32_t dstb = sb + SM_B(1 - s);
#pragma unroll
            for (int t = 0; t < 8; ++t) {
                int e = t * 256 + tid;
                int r = e >> 5, j = e & 31;
                cpa16(dstb + r * PADB + j * 16, csrc + (size_t)r * D + j * 8);
            }
            CP_COMMIT();
            CP_WAIT(1);
        } else {
            CP_WAIT(0);
        }
        __syncthreads();

        const uint32_t bufb = sb + SM_B(s) + bLaneOff;

        float acc[2][4][4];
#pragma unroll
        for (int mt = 0; mt < 2; ++mt)
#pragma unroll
            for (int nt = 0; nt < 4; ++nt)
#pragma unroll
                for (int q = 0; q < 4; ++q) acc[mt][nt][q] = 0.f;

#pragma unroll
        for (int ks = 0; ks < 16; ++ks) {
            uint32_t b0[4], b1[4];
            ldsm_x4(b0, bufb + ks * 32);                 // codes +0..15
            ldsm_x4(b1, bufb + 16 * PADB + ks * 32);     // codes +16..31
#pragma unroll
            for (int mt = 0; mt < 2; ++mt) {
                mma_bf16(acc[mt][0], aR[mt][ks], b0[0], b0[1]);
                mma_bf16(acc[mt][1], aR[mt][ks], b0[2], b0[3]);
                mma_bf16(acc[mt][2], aR[mt][ks], b1[0], b1[1]);
                mma_bf16(acc[mt][3], aR[mt][ks], b1[2], b1[3]);
            }
        }

        // ---- top-2 update (lazy index) ----
        const int cbase0 = i * CHUNK + warpN * 32 + tg * 2;
#pragma unroll
        for (int mt = 0; mt < 2; ++mt) {
#pragma unroll
            for (int nt = 0; nt < 4; ++nt) {
#pragma unroll
                for (int q = 0; q < 4; ++q) {
                    const int sl = mt * 2 + (q >> 1);
                    const float v = acc[mt][nt][q];
                    if (v > bv[sl][1]) {
                        const int ci = cbase0 + nt * 8 + (q & 1);
                        if (v > bv[sl][0]) {
                            bv[sl][1] = bv[sl][0]; bi[sl][1] = bi[sl][0];
                            bv[sl][0] = v;         bi[sl][0] = ci;
                        } else {
                            bv[sl][1] = v;         bi[sl][1] = ci;
                        }
                    }
                }
            }
        }
        __syncthreads();
    }

    // ---- merge: 8 owners x top2 per row -> global top4 ----
    float* mv = reinterpret_cast<float*>(sm);           // 16*128 floats = 8KB
    int*   mi = reinterpret_cast<int*>(sm + 8192);      // 8KB
    const int owner = warpN * 4 + tg;                   // 0..7
#pragma unroll
    for (int sl = 0; sl < 4; ++sl) {
        const int srow = warpM * 32 + (sl >> 1) * 16 + (sl & 1) * 8 + g;
#pragma unroll
        for (int j = 0; j < 2; ++j) {
            mv[(owner * 2 + j) * 128 + srow] = bv[sl][j];
            mi[(owner * 2 + j) * 128 + srow] = bi[sl][j];
        }
    }
    __syncthreads();
    if (tid < 128) {
        float fv0=-3.4e38f, fv1=-3.4e38f, fv2=-3.4e38f, fv3=-3.4e38f;
        int   fi0=0, fi1=0, fi2=0, fi3=0;
#pragma unroll
        for (int e = 0; e < 16; ++e) {
            float v = mv[e * 128 + tid];
            if (v > fv3) {
                int ci = mi[e * 128 + tid];
                if (v > fv0)      { fv3=fv2;fi3=fi2; fv2=fv1;fi2=fi1; fv1=fv0;fi1=fi0; fv0=v;fi0=ci; }
                else if (v > fv1) { fv3=fv2;fi3=fi2; fv2=fv1;fi2=fi1; fv1=v;fi1=ci; }
                else if (v > fv2) { fv3=fv2;fi3=fi2; fv2=v;fi2=ci; }
                else              { fv3=v;fi3=ci; }
            }
        }
        const int r = row0 + tid;
        g_cand[r * 4 + 0] = fi0;
        g_cand[r * 4 + 1] = fi1;
        g_cand[r * 4 + 2] = fi2;
        g_cand[r * 4 + 3] = fi3;
    }
}

// ================= stage 2: exact fp32 rescore, 4 lanes per row =================
// Each lane: A = exact sequential sum(z^2) (identical op order to R1), one
// candidate's sequential-k fmaf dot, score = fl(fl(A-2B)+C);
// min-by-(value,index) via shfl butterfly.
__global__ void k_rescore(const float* __restrict__ z, const float* __restrict__ cb, int n) {
    int gid = blockIdx.x * blockDim.x + threadIdx.x;
    int row = gid >> 2, m = gid & 3;
    if (row >= n) return;
    const float4* zr = reinterpret_cast<const float4*>(z + (size_t)row * D);

    int c = g_cand[row * 4 + m];
    const float4* cr = reinterpret_cast<const float4*>(cb + (size_t)c * D);

    float A = 0.f, acc = 0.f;
#pragma unroll 8
    for (int i = 0; i < D / 4; ++i) {
        float4 a = zr[i];
        float4 b = cr[i];
        A = __fadd_rn(A, __fmul_rn(a.x, a.x));
        A = __fadd_rn(A, __fmul_rn(a.y, a.y));
        A = __fadd_rn(A, __fmul_rn(a.z, a.z));
        A = __fadd_rn(A, __fmul_rn(a.w, a.w));
        acc = __fmaf_rn(a.x, b.x, acc);
        acc = __fmaf_rn(a.y, b.y, acc);
        acc = __fmaf_rn(a.z, b.z, acc);
        acc = __fmaf_rn(a.w, b.w, acc);
    }
    float s = __fadd_rn(__fmaf_rn(-2.f, acc, A), g_C[c]);

#pragma unroll
    for (int o = 1; o < 4; o <<= 1) {
        float sv = __shfl_xor_sync(0xffffffffu, s, o);
        int   ci = __shfl_xor_sync(0xffffffffu, c, o);
        if (sv < s || (sv == s && ci < c)) { s = sv; c = ci; }
    }
    if (m == 0) g_idx[row] = c;
}

// ================= finish: gather, z_q, per-row d^2, indices =================
__global__ void k_finish(const float* __restrict__ z, const float* __restrict__ cb,
                         float* __restrict__ zq, float* __restrict__ idxout) {
    const int row = blockIdx.x;
    const int t = threadIdx.x;          // 128 threads, 2 elems each
    const int code = g_idx[row];
    const float2 zp = reinterpret_cast<const float2*>(z + (size_t)row * D)[t];
    const float2 cp = reinterpret_cast<const float2*>(cb + (size_t)code * D)[t];
    float d0 = __fsub_rn(cp.x, zp.x);
    float d1 = __fsub_rn(cp.y, zp.y);
    float ss = __fadd_rn(__fmul_rn(d0, d0), __fmul_rn(d1, d1));

    __shared__ float red[4];
#pragma unroll
    for (int o = 16; o > 0; o >>= 1)
        ss = __fadd_rn(ss, __shfl_xor_sync(0xffffffffu, ss, o));
    if ((t & 31) == 0) red[t >> 5] = ss;
    __syncthreads();
    float ssum = __fadd_rn(__fadd_rn(red[0], red[1]), __fadd_rn(red[2], red[3]));

    float mag = __fsqrt_rn(ssum);
    float den = __fadd_rn(mag, 1e-8f);
    float q0 = __fadd_rn(zp.x, __fmul_rn(mag, __fdiv_rn(d0, den)));
    float q1 = __fadd_rn(zp.y, __fmul_rn(mag, __fdiv_rn(d1, den)));
    float2 o; o.x = q0; o.y = q1;
    reinterpret_cast<float2*>(zq + (size_t)row * D)[t] = o;
    if (t == 0) {
        g_rowss[row] = ssum;
        idxout[row] = (float)code;
    }
}

// ================= loss = 1.25 * mean(d^2) =================
__global__ void k_loss(float* __restrict__ out_loss, int n) {
    __shared__ double sred[256];
    double s = 0.0;
    for (int i = threadIdx.x; i < n; i += 256) s += (double)g_rowss[i];
    sred[threadIdx.x] = s;
    __syncthreads();
    for (int o = 128; o > 0; o >>= 1) {
        if (threadIdx.x < o) sred[threadIdx.x] += sred[threadIdx.x + o];
        __syncthreads();
    }
    if (threadIdx.x == 0) {
        double mean = sred[0] / ((double)n * (double)D);
        out_loss[0] = (float)(1.25 * mean);
    }
}

extern "C" void kernel_launch(void* const* d_in, const int* in_sizes, int n_in,
                              void* d_out, int out_size) {
    const float* z  = (const float*)d_in[0];
    const float* cb = (const float*)d_in[1];
    const int n = in_sizes[0] / D;   // 16384
    const int K = in_sizes[1] / D;   // 8192

    float* out    = (float*)d_out;
    float* zq     = out;
    float* loss   = out + (size_t)n * D;
    float* idxout = loss + 1;

    cudaFuncSetAttribute(k_gemm_topk, cudaFuncAttributeMaxDynamicSharedMemorySize, SM_TOT);

    const int nz4 = n * D / 4, nc4 = K * D / 4;
    k_cvt<<<(nz4 + nc4 + 255) / 256, 256>>>(z, cb, nz4, nc4);
    k_sumsq_cb<<<(K + 255) / 256, 256>>>(cb, K);
    k_gemm_topk<<<n / 128, 256, SM_TOT>>>(K);
    k_rescore<<<(n * 4 + 255) / 256, 256>>>(z, cb, n);
    k_finish<<<n, 128>>>(z, cb, zq, idxout);
    k_loss<<<1, 256>>>(loss, n);
}